// round 2
// baseline (speedup 1.0000x reference)
#include <cuda_runtime.h>
#include <math.h>

// Problem constants (B=2, S=2048 -> T=4096; H=1024; F=512; E=8; TOPK=2)
#define T_TOK 4096
#define H_DIM 1024
#define F_DIM 512
#define E_NUM 8

// GEMM tiling
#define BM 64
#define BN 64
#define BK 16

// ---------------- scratch (device globals; no runtime allocation) -----------
__device__ int   g_count[E_NUM];                    // tokens routed to each expert
__device__ int   g_tok[E_NUM][T_TOK];               // token index per slot
__device__ float g_wt [E_NUM][T_TOK];               // combine weight per slot
__device__ float g_act[E_NUM][T_TOK][F_DIM];        // silu(gate)*up*w scratch (64MB)

// ---------------- init: zero expert counters each launch --------------------
__global__ void init_kernel() {
    if (threadIdx.x < E_NUM) g_count[threadIdx.x] = 0;
}

// ---------------- router: logits -> top2 -> normalized weights --------------
// One warp per token.
__global__ __launch_bounds__(256) void router_kernel(
    const float* __restrict__ x, const float* __restrict__ Wr)
{
    int warp = (blockIdx.x * blockDim.x + threadIdx.x) >> 5;
    int lane = threadIdx.x & 31;
    if (warp >= T_TOK) return;

    const float* xr = x + (size_t)warp * H_DIM;
    float acc[E_NUM];
#pragma unroll
    for (int e = 0; e < E_NUM; e++) acc[e] = 0.f;

    for (int h = lane; h < H_DIM; h += 32) {
        float xv = xr[h];
        const float* wr = Wr + (size_t)h * E_NUM;
#pragma unroll
        for (int e = 0; e < E_NUM; e++) acc[e] += xv * wr[e];
    }
#pragma unroll
    for (int e = 0; e < E_NUM; e++) {
#pragma unroll
        for (int off = 16; off; off >>= 1)
            acc[e] += __shfl_xor_sync(0xffffffff, acc[e], off);
    }

    if (lane == 0) {
        // top-1 (strict > keeps lowest index on ties, matching lax.top_k)
        int e1 = 0;
#pragma unroll
        for (int e = 1; e < E_NUM; e++) if (acc[e] > acc[e1]) e1 = e;
        // top-2
        int e2 = -1;
#pragma unroll
        for (int e = 0; e < E_NUM; e++) {
            if (e == e1) continue;
            if (e2 < 0 || acc[e] > acc[e2]) e2 = e;
        }
        float l1 = acc[e1], l2 = acc[e2];
        // normalized top-2 softmax: p1 = e^l1/(e^l1+e^l2)
        float p2 = 1.f / (1.f + expf(l1 - l2));
        float p1 = 1.f - p2;

        int pos1 = atomicAdd(&g_count[e1], 1);
        g_tok[e1][pos1] = warp; g_wt[e1][pos1] = p1;
        int pos2 = atomicAdd(&g_count[e2], 1);
        g_tok[e2][pos2] = warp; g_wt[e2][pos2] = p2;
    }
}

// ---------------- gate/up GEMMs + SwiGLU + combine weight -------------------
// C1 = Xg @ Wg_e, C2 = Xg @ Wu_e ; act = silu(C1)*C2*w  -> g_act
// grid: (F/BN, T/BM, E); 256 threads; 4x4 microtile, two accumulators.
__global__ __launch_bounds__(256) void gateup_kernel(
    const float* __restrict__ x,
    const float* __restrict__ Wg,
    const float* __restrict__ Wu)
{
    int e = blockIdx.z;
    int n_e = g_count[e];
    int row0 = blockIdx.y * BM;
    if (row0 >= n_e) return;
    int n0 = blockIdx.x * BN;

    __shared__ float As[BM][BK];
    __shared__ float Bg[BK][BN];
    __shared__ float Bu[BK][BN];
    __shared__ int   toks[BM];

    int tid = threadIdx.x;
    if (tid < BM) {
        int m = row0 + tid;
        toks[tid] = (m < n_e) ? g_tok[e][m] : 0;   // clamp: safe x read
    }
    __syncthreads();

    int ty = tid >> 4, tx = tid & 15;
    float accg[4][4], accu[4][4];
#pragma unroll
    for (int i = 0; i < 4; i++)
#pragma unroll
        for (int j = 0; j < 4; j++) { accg[i][j] = 0.f; accu[i][j] = 0.f; }

    const float* Wge = Wg + (size_t)e * H_DIM * F_DIM;
    const float* Wue = Wu + (size_t)e * H_DIM * F_DIM;

    int arow = tid >> 2;           // 0..63
    int acol = (tid & 3) * 4;      // 0,4,8,12
    int brow = tid >> 4;           // 0..15
    int bcol = (tid & 15) * 4;     // 0..60

    for (int k0 = 0; k0 < H_DIM; k0 += BK) {
        const float4 av = *(const float4*)(x + (size_t)toks[arow] * H_DIM + k0 + acol);
        *(float4*)&As[arow][acol] = av;
        const float4 bgv = *(const float4*)(Wge + (size_t)(k0 + brow) * F_DIM + n0 + bcol);
        const float4 buv = *(const float4*)(Wue + (size_t)(k0 + brow) * F_DIM + n0 + bcol);
        *(float4*)&Bg[brow][bcol] = bgv;
        *(float4*)&Bu[brow][bcol] = buv;
        __syncthreads();
#pragma unroll
        for (int kk = 0; kk < BK; kk++) {
            float a[4];
#pragma unroll
            for (int i = 0; i < 4; i++) a[i] = As[ty * 4 + i][kk];
            float4 b1 = *(float4*)&Bg[kk][tx * 4];
            float4 b2 = *(float4*)&Bu[kk][tx * 4];
            float bg4[4] = {b1.x, b1.y, b1.z, b1.w};
            float bu4[4] = {b2.x, b2.y, b2.z, b2.w};
#pragma unroll
            for (int i = 0; i < 4; i++) {
#pragma unroll
                for (int j = 0; j < 4; j++) {
                    accg[i][j] += a[i] * bg4[j];
                    accu[i][j] += a[i] * bu4[j];
                }
            }
        }
        __syncthreads();
    }

#pragma unroll
    for (int i = 0; i < 4; i++) {
        int m = row0 + ty * 4 + i;
        if (m >= n_e) continue;
        float w = g_wt[e][m];
#pragma unroll
        for (int j = 0; j < 4; j++) {
            float g = accg[i][j], u = accu[i][j];
            float s = g / (1.f + expf(-g));     // silu
            g_act[e][m][n0 + tx * 4 + j] = s * u * w;
        }
    }
}

// ---------------- down GEMM + scatter-add --------------------------------
// out[t] += act_slot @ Wd_e ; grid: (H/BN, T/BM, E)
__global__ __launch_bounds__(256) void down_kernel(
    const float* __restrict__ Wd, float* __restrict__ out)
{
    int e = blockIdx.z;
    int n_e = g_count[e];
    int row0 = blockIdx.y * BM;
    if (row0 >= n_e) return;
    int n0 = blockIdx.x * BN;

    __shared__ float As[BM][BK];
    __shared__ float Bs[BK][BN];

    int tid = threadIdx.x;
    int ty = tid >> 4, tx = tid & 15;
    float acc[4][4];
#pragma unroll
    for (int i = 0; i < 4; i++)
#pragma unroll
        for (int j = 0; j < 4; j++) acc[i][j] = 0.f;

    const float* Wde = Wd + (size_t)e * F_DIM * H_DIM;

    int arow = tid >> 2;
    int acol = (tid & 3) * 4;
    int brow = tid >> 4;
    int bcol = (tid & 15) * 4;

    for (int k0 = 0; k0 < F_DIM; k0 += BK) {
        *(float4*)&As[arow][acol] =
            *(const float4*)&g_act[e][row0 + arow][k0 + acol];  // stale rows discarded in epilogue
        *(float4*)&Bs[brow][bcol] =
            *(const float4*)(Wde + (size_t)(k0 + brow) * H_DIM + n0 + bcol);
        __syncthreads();
#pragma unroll
        for (int kk = 0; kk < BK; kk++) {
            float a[4];
#pragma unroll
            for (int i = 0; i < 4; i++) a[i] = As[ty * 4 + i][kk];
            float4 b = *(float4*)&Bs[kk][tx * 4];
            float b4[4] = {b.x, b.y, b.z, b.w};
#pragma unroll
            for (int i = 0; i < 4; i++)
#pragma unroll
                for (int j = 0; j < 4; j++)
                    acc[i][j] += a[i] * b4[j];
        }
        __syncthreads();
    }

#pragma unroll
    for (int i = 0; i < 4; i++) {
        int m = row0 + ty * 4 + i;
        if (m >= n_e) continue;
        int t = g_tok[e][m];
        float* orow = out + (size_t)t * H_DIM + n0 + tx * 4;
#pragma unroll
        for (int j = 0; j < 4; j++)
            atomicAdd(&orow[j], acc[i][j]);
    }
}

// ---------------- launch ----------------------------------------------------
extern "C" void kernel_launch(void* const* d_in, const int* in_sizes, int n_in,
                              void* d_out, int out_size)
{
    const float* x  = (const float*)d_in[0];
    const float* Wr = (const float*)d_in[1];
    const float* Wg = (const float*)d_in[2];
    const float* Wu = (const float*)d_in[3];
    const float* Wd = (const float*)d_in[4];
    float* out = (float*)d_out;

    cudaMemsetAsync(out, 0, (size_t)out_size * sizeof(float));

    init_kernel<<<1, 32>>>();
    router_kernel<<<T_TOK / 8, 256>>>(x, Wr);   // 8 warps/block, 1 token/warp

    dim3 g2(F_DIM / BN, T_TOK / BM, E_NUM);
    gateup_kernel<<<g2, 256>>>(x, Wg, Wu);

    dim3 g3(H_DIM / BN, T_TOK / BM, E_NUM);
    down_kernel<<<g3, 256>>>(Wd, out);
}

// round 5
// speedup vs baseline: 2.4594x; 2.4594x over previous
#include <cuda_runtime.h>
#include <math.h>
#include <stdint.h>

// Problem constants (B=2, S=2048 -> T=4096; H=1024; F=512; E=8; TOPK=2)
#define T_TOK 4096
#define H_DIM 1024
#define F_DIM 512
#define E_NUM 8

// ---------------------------------------------------------------------------
// Helpers
// ---------------------------------------------------------------------------
__device__ __forceinline__ float f2tf32f(float f) {
    uint32_t r;
    asm("cvt.rna.tf32.f32 %0, %1;" : "=r"(r) : "f"(f));
    return __uint_as_float(r);
}

#define CP_ASYNC16(dst_u32, src_ptr) \
    asm volatile("cp.async.cg.shared.global [%0], [%1], 16;" \
        :: "r"(dst_u32), "l"(src_ptr))
#define CP_COMMIT() asm volatile("cp.async.commit_group;")
#define CP_WAIT(n)  asm volatile("cp.async.wait_group %0;" :: "n"(n))

// m16n8k8 tf32 MMA: d += a*b  (row.col, f32 accum)
__device__ __forceinline__ void mma_tf32(float* d, const uint32_t* a, const uint32_t* b) {
    asm volatile(
        "mma.sync.aligned.m16n8k8.row.col.f32.tf32.tf32.f32 "
        "{%0,%1,%2,%3}, {%4,%5,%6,%7}, {%8,%9}, {%0,%1,%2,%3};"
        : "+f"(d[0]), "+f"(d[1]), "+f"(d[2]), "+f"(d[3])
        : "r"(a[0]), "r"(a[1]), "r"(a[2]), "r"(a[3]), "r"(b[0]), "r"(b[1]));
}

// ---------------------------------------------------------------------------
// Scratch (device globals; no runtime allocation)
// ---------------------------------------------------------------------------
__device__ int   g_count[E_NUM];
__device__ int   g_tok[E_NUM][T_TOK];
__device__ float g_wt [E_NUM][T_TOK];
__device__ float g_x  [T_TOK][H_DIM];             // tf32-rounded x
__device__ float g_act[E_NUM][T_TOK][F_DIM];      // tf32-rounded activations
__device__ float g_wgt[E_NUM][F_DIM][H_DIM];      // Wg^T, tf32-rounded
__device__ float g_wut[E_NUM][F_DIM][H_DIM];      // Wu^T, tf32-rounded
__device__ float g_wdt[E_NUM][H_DIM][F_DIM];      // Wd^T, tf32-rounded

// ---------------------------------------------------------------------------
__global__ void init_kernel() {
    if (threadIdx.x < E_NUM) g_count[threadIdx.x] = 0;
}

// x -> tf32-rounded copy (vectorized)
__global__ __launch_bounds__(256) void round_x_kernel(const float* __restrict__ x) {
    int i = blockIdx.x * 256 + threadIdx.x;
    float4 v = ((const float4*)x)[i];
    v.x = f2tf32f(v.x); v.y = f2tf32f(v.y);
    v.z = f2tf32f(v.z); v.w = f2tf32f(v.w);
    ((float4*)&g_x[0][0])[i] = v;
}

// Router: one warp per token, top-2 normalized softmax, scatter to expert lists
__global__ __launch_bounds__(256) void router_kernel(
    const float* __restrict__ x, const float* __restrict__ Wr)
{
    int warp = (blockIdx.x * blockDim.x + threadIdx.x) >> 5;
    int lane = threadIdx.x & 31;
    if (warp >= T_TOK) return;

    const float* xr = x + (size_t)warp * H_DIM;
    float acc[E_NUM];
#pragma unroll
    for (int e = 0; e < E_NUM; e++) acc[e] = 0.f;

    for (int h = lane; h < H_DIM; h += 32) {
        float xv = xr[h];
        const float* wr = Wr + (size_t)h * E_NUM;
#pragma unroll
        for (int e = 0; e < E_NUM; e++) acc[e] += xv * wr[e];
    }
#pragma unroll
    for (int e = 0; e < E_NUM; e++) {
#pragma unroll
        for (int off = 16; off; off >>= 1)
            acc[e] += __shfl_xor_sync(0xffffffff, acc[e], off);
    }

    if (lane == 0) {
        int e1 = 0;
#pragma unroll
        for (int e = 1; e < E_NUM; e++) if (acc[e] > acc[e1]) e1 = e;
        int e2 = -1;
#pragma unroll
        for (int e = 0; e < E_NUM; e++) {
            if (e == e1) continue;
            if (e2 < 0 || acc[e] > acc[e2]) e2 = e;
        }
        float l1 = acc[e1], l2 = acc[e2];
        float p2 = 1.f / (1.f + expf(l1 - l2));
        float p1 = 1.f - p2;

        int pos1 = atomicAdd(&g_count[e1], 1);
        g_tok[e1][pos1] = warp; g_wt[e1][pos1] = p1;
        int pos2 = atomicAdd(&g_count[e2], 1);
        g_tok[e2][pos2] = warp; g_wt[e2][pos2] = p2;
    }
}

// Transpose + tf32 round per expert: in [E][R][C] -> out [E][C][R]
__global__ __launch_bounds__(256) void transpose_round_kernel(
    const float* __restrict__ in, float* __restrict__ out, int R, int C)
{
    __shared__ float tile[32][33];
    int e = blockIdx.z;
    const float* pin = in + (size_t)e * R * C;
    float* pout = out + (size_t)e * R * C;
    int c0 = blockIdx.x * 32, r0 = blockIdx.y * 32;
    int tx = threadIdx.x, ty = threadIdx.y;
#pragma unroll
    for (int dy = ty; dy < 32; dy += 8)
        tile[dy][tx] = f2tf32f(pin[(size_t)(r0 + dy) * C + c0 + tx]);
    __syncthreads();
#pragma unroll
    for (int dy = ty; dy < 32; dy += 8)
        pout[(size_t)(c0 + dy) * R + r0 + tx] = tile[tx][dy];
}

// ---------------------------------------------------------------------------
// Gate+Up mma.sync GEMM.
// CTA: M=128 token slots x N=64 f-cols, computing BOTH gate and up.
// K=H=1024 in 32-float chunks, 2-stage cp.async pipeline.
// Warp grid 4(M) x 2(N): each warp 32 rows x 32 cols, per matrix.
// Smem stage: A[128][36] + Bg[64][36] + Bu[64][36] floats (pad 36 -> no conflicts)
// ---------------------------------------------------------------------------
#define GU_STAGE_F (128 * 36 + 2 * 64 * 36)     // 9216 floats
#define GEMM_SMEM_BYTES (GU_STAGE_F * 4 * 2)    // 73728 bytes (down uses same size)

__global__ __launch_bounds__(256) void gateup_mma_kernel()
{
    int e = blockIdx.z;
    int n_e = g_count[e];
    int row0 = blockIdx.y * 128;
    if (row0 >= n_e) return;
    int n0 = blockIdx.x * 64;

    extern __shared__ float sm[];
    __shared__ int toks[128];
    int tid = threadIdx.x;
    if (tid < 128) {
        int m = row0 + tid;
        toks[tid] = g_tok[e][m < n_e ? m : (n_e - 1)];
    }
    __syncthreads();

    const float* wg_e = &g_wgt[e][0][0];
    const float* wu_e = &g_wut[e][0][0];

    int wid = tid >> 5, lane = tid & 31;
    int wm = wid & 3, wn = wid >> 2;
    int g = lane >> 2, t = lane & 3;

    float accg[2][4][4], accu[2][4][4];
#pragma unroll
    for (int mi = 0; mi < 2; mi++)
#pragma unroll
        for (int nj = 0; nj < 4; nj++)
#pragma unroll
            for (int q = 0; q < 4; q++) { accg[mi][nj][q] = 0.f; accu[mi][nj][q] = 0.f; }

    const int NCH = H_DIM / 32;

    // ---- stage loader (inlined twice) ----
#define GU_LOAD(cc, stage) do { \
        int k0 = (cc) * 32; \
        float* base = sm + (stage) * GU_STAGE_F; \
        uint32_t sA = (uint32_t)__cvta_generic_to_shared(base); \
        uint32_t sG = (uint32_t)__cvta_generic_to_shared(base + 128 * 36); \
        uint32_t sU = (uint32_t)__cvta_generic_to_shared(base + 128 * 36 + 64 * 36); \
        _Pragma("unroll") \
        for (int i = 0; i < 4; i++) { \
            int idx = tid + i * 256; int r = idx >> 3, c4 = idx & 7; \
            CP_ASYNC16(sA + (uint32_t)(r * 36 + c4 * 4) * 4, &g_x[toks[r]][k0 + c4 * 4]); \
        } \
        _Pragma("unroll") \
        for (int i = 0; i < 2; i++) { \
            int idx = tid + i * 256; int r = idx >> 3, c4 = idx & 7; \
            CP_ASYNC16(sG + (uint32_t)(r * 36 + c4 * 4) * 4, wg_e + (size_t)(n0 + r) * H_DIM + k0 + c4 * 4); \
            CP_ASYNC16(sU + (uint32_t)(r * 36 + c4 * 4) * 4, wu_e + (size_t)(n0 + r) * H_DIM + k0 + c4 * 4); \
        } \
        CP_COMMIT(); \
    } while (0)

    GU_LOAD(0, 0);

#pragma unroll 1
    for (int c = 0; c < NCH; c++) {
        int stage = c & 1;
        if (c + 1 < NCH) { GU_LOAD(c + 1, (c + 1) & 1); CP_WAIT(1); }
        else            { CP_WAIT(0); }
        __syncthreads();

        const float* A  = sm + stage * GU_STAGE_F;
        const float* Bg = A + 128 * 36;
        const float* Bu = Bg + 64 * 36;

#pragma unroll
        for (int ks = 0; ks < 4; ks++) {
            int kb = ks * 8;
            uint32_t a[2][4];
#pragma unroll
            for (int mi = 0; mi < 2; mi++) {
                int r = wm * 32 + mi * 16 + g;
                a[mi][0] = __float_as_uint(A[r * 36 + kb + t]);
                a[mi][1] = __float_as_uint(A[(r + 8) * 36 + kb + t]);
                a[mi][2] = __float_as_uint(A[r * 36 + kb + t + 4]);
                a[mi][3] = __float_as_uint(A[(r + 8) * 36 + kb + t + 4]);
            }
#pragma unroll
            for (int nj = 0; nj < 4; nj++) {
                int n = wn * 32 + nj * 8 + g;
                uint32_t bg[2], bu[2];
                bg[0] = __float_as_uint(Bg[n * 36 + kb + t]);
                bg[1] = __float_as_uint(Bg[n * 36 + kb + t + 4]);
                bu[0] = __float_as_uint(Bu[n * 36 + kb + t]);
                bu[1] = __float_as_uint(Bu[n * 36 + kb + t + 4]);
#pragma unroll
                for (int mi = 0; mi < 2; mi++) {
                    mma_tf32(accg[mi][nj], a[mi], bg);
                    mma_tf32(accu[mi][nj], a[mi], bu);
                }
            }
        }
        __syncthreads();
    }
#undef GU_LOAD

    // Epilogue: act = silu(gate)*up*w, tf32-rounded -> g_act
#pragma unroll
    for (int mi = 0; mi < 2; mi++) {
#pragma unroll
        for (int half = 0; half < 2; half++) {
            int m = row0 + wm * 32 + mi * 16 + g + half * 8;
            if (m >= n_e) continue;
            float w = g_wt[e][m];
            float* dst = &g_act[e][m][n0 + wn * 32];
#pragma unroll
            for (int nj = 0; nj < 4; nj++) {
                float g0 = accg[mi][nj][half * 2 + 0];
                float g1 = accg[mi][nj][half * 2 + 1];
                float u0 = accu[mi][nj][half * 2 + 0];
                float u1 = accu[mi][nj][half * 2 + 1];
                float s0 = g0 / (1.f + expf(-g0)) * u0 * w;
                float s1 = g1 / (1.f + expf(-g1)) * u1 * w;
                float2 o = make_float2(f2tf32f(s0), f2tf32f(s1));
                *(float2*)(dst + nj * 8 + 2 * t) = o;
            }
        }
    }
}

// ---------------------------------------------------------------------------
// Down mma.sync GEMM + scatter-add.
// CTA: M=128 slots x N=128 h-cols, K=F=512 in 32-float chunks.
// Warp grid 4(M) x 2(N): each warp 32 rows x 64 cols.
// Smem stage: A[128][36] + B[128][36]
// ---------------------------------------------------------------------------
#define DN_STAGE_F (128 * 36 + 128 * 36)        // 9216 floats (same size)

__global__ __launch_bounds__(256) void down_mma_kernel(float* __restrict__ out)
{
    int e = blockIdx.z;
    int n_e = g_count[e];
    int row0 = blockIdx.y * 128;
    if (row0 >= n_e) return;
    int n0 = blockIdx.x * 128;

    extern __shared__ float sm[];
    int tid = threadIdx.x;

    const float* a_e = &g_act[e][row0][0];
    const float* b_e = &g_wdt[e][n0][0];

    int wid = tid >> 5, lane = tid & 31;
    int wm = wid & 3, wn = wid >> 2;
    int g = lane >> 2, t = lane & 3;

    float acc[2][8][4];
#pragma unroll
    for (int mi = 0; mi < 2; mi++)
#pragma unroll
        for (int nj = 0; nj < 8; nj++)
#pragma unroll
            for (int q = 0; q < 4; q++) acc[mi][nj][q] = 0.f;

    const int NCH = F_DIM / 32;

#define DN_LOAD(cc, stage) do { \
        int k0 = (cc) * 32; \
        float* base = sm + (stage) * DN_STAGE_F; \
        uint32_t sA = (uint32_t)__cvta_generic_to_shared(base); \
        uint32_t sB = (uint32_t)__cvta_generic_to_shared(base + 128 * 36); \
        _Pragma("unroll") \
        for (int i = 0; i < 4; i++) { \
            int idx = tid + i * 256; int r = idx >> 3, c4 = idx & 7; \
            CP_ASYNC16(sA + (uint32_t)(r * 36 + c4 * 4) * 4, a_e + (size_t)r * F_DIM + k0 + c4 * 4); \
            CP_ASYNC16(sB + (uint32_t)(r * 36 + c4 * 4) * 4, b_e + (size_t)r * F_DIM + k0 + c4 * 4); \
        } \
        CP_COMMIT(); \
    } while (0)

    DN_LOAD(0, 0);

#pragma unroll 1
    for (int c = 0; c < NCH; c++) {
        int stage = c & 1;
        if (c + 1 < NCH) { DN_LOAD(c + 1, (c + 1) & 1); CP_WAIT(1); }
        else            { CP_WAIT(0); }
        __syncthreads();

        const float* A = sm + stage * DN_STAGE_F;
        const float* B = A + 128 * 36;

#pragma unroll
        for (int ks = 0; ks < 4; ks++) {
            int kb = ks * 8;
            uint32_t a[2][4];
#pragma unroll
            for (int mi = 0; mi < 2; mi++) {
                int r = wm * 32 + mi * 16 + g;
                a[mi][0] = __float_as_uint(A[r * 36 + kb + t]);
                a[mi][1] = __float_as_uint(A[(r + 8) * 36 + kb + t]);
                a[mi][2] = __float_as_uint(A[r * 36 + kb + t + 4]);
                a[mi][3] = __float_as_uint(A[(r + 8) * 36 + kb + t + 4]);
            }
#pragma unroll
            for (int nj = 0; nj < 8; nj++) {
                int n = wn * 64 + nj * 8 + g;
                uint32_t b[2];
                b[0] = __float_as_uint(B[n * 36 + kb + t]);
                b[1] = __float_as_uint(B[n * 36 + kb + t + 4]);
#pragma unroll
                for (int mi = 0; mi < 2; mi++)
                    mma_tf32(acc[mi][nj], a[mi], b);
            }
        }
        __syncthreads();
    }
#undef DN_LOAD

    // Epilogue: scatter-add into out rows
#pragma unroll
    for (int mi = 0; mi < 2; mi++) {
#pragma unroll
        for (int half = 0; half < 2; half++) {
            int m = row0 + wm * 32 + mi * 16 + g + half * 8;
            if (m >= n_e) continue;
            int tk = g_tok[e][m];
            float* dst = out + (size_t)tk * H_DIM + n0 + wn * 64;
#pragma unroll
            for (int nj = 0; nj < 8; nj++) {
                atomicAdd(dst + nj * 8 + 2 * t,     acc[mi][nj][half * 2 + 0]);
                atomicAdd(dst + nj * 8 + 2 * t + 1, acc[mi][nj][half * 2 + 1]);
            }
        }
    }
}

// ---------------------------------------------------------------------------
extern "C" void kernel_launch(void* const* d_in, const int* in_sizes, int n_in,
                              void* d_out, int out_size)
{
    const float* x  = (const float*)d_in[0];
    const float* Wr = (const float*)d_in[1];
    const float* Wg = (const float*)d_in[2];
    const float* Wu = (const float*)d_in[3];
    const float* Wd = (const float*)d_in[4];
    float* out = (float*)d_out;

    cudaFuncSetAttribute(gateup_mma_kernel, cudaFuncAttributeMaxDynamicSharedMemorySize, GEMM_SMEM_BYTES);
    cudaFuncSetAttribute(down_mma_kernel,   cudaFuncAttributeMaxDynamicSharedMemorySize, GEMM_SMEM_BYTES);

    cudaMemsetAsync(out, 0, (size_t)out_size * sizeof(float));

    init_kernel<<<1, 32>>>();
    round_x_kernel<<<T_TOK * H_DIM / 4 / 256, 256>>>(x);
    router_kernel<<<T_TOK / 8, 256>>>(x, Wr);

    float* wgt = nullptr; cudaGetSymbolAddress((void**)&wgt, g_wgt);
    float* wut = nullptr; cudaGetSymbolAddress((void**)&wut, g_wut);
    float* wdt = nullptr; cudaGetSymbolAddress((void**)&wdt, g_wdt);

    dim3 tb(32, 8);
    transpose_round_kernel<<<dim3(F_DIM / 32, H_DIM / 32, E_NUM), tb>>>(Wg, wgt, H_DIM, F_DIM);
    transpose_round_kernel<<<dim3(F_DIM / 32, H_DIM / 32, E_NUM), tb>>>(Wu, wut, H_DIM, F_DIM);
    transpose_round_kernel<<<dim3(H_DIM / 32, F_DIM / 32, E_NUM), tb>>>(Wd, wdt, F_DIM, H_DIM);

    dim3 g2(F_DIM / 64, T_TOK / 128, E_NUM);
    gateup_mma_kernel<<<g2, 256, GEMM_SMEM_BYTES>>>();

    dim3 g3(H_DIM / 128, T_TOK / 128, E_NUM);
    down_mma_kernel<<<g3, 256, GEMM_SMEM_BYTES>>>(out);
}

// round 7
// speedup vs baseline: 2.7995x; 1.1383x over previous
#include <cuda_runtime.h>
#include <math.h>
#include <stdint.h>

// Problem constants (B=2, S=2048 -> T=4096; H=1024; F=512; E=8; TOPK=2)
#define T_TOK 4096
#define H_DIM 1024
#define F_DIM 512
#define E_NUM 8

// ---------------------------------------------------------------------------
// Helpers
// ---------------------------------------------------------------------------
__device__ __forceinline__ float f2tf32f(float f) {
    uint32_t r;
    asm("cvt.rna.tf32.f32 %0, %1;" : "=r"(r) : "f"(f));
    return __uint_as_float(r);
}
__device__ __forceinline__ uint32_t f2tf32u(float f) {
    uint32_t r;
    asm("cvt.rna.tf32.f32 %0, %1;" : "=r"(r) : "f"(f));
    return r;
}

#define CP_ASYNC16(dst_u32, src_ptr) \
    asm volatile("cp.async.cg.shared.global [%0], [%1], 16;" \
        :: "r"(dst_u32), "l"(src_ptr))
#define CP_COMMIT() asm volatile("cp.async.commit_group;")
#define CP_WAIT(n)  asm volatile("cp.async.wait_group %0;" :: "n"(n))

// m16n8k8 tf32 MMA: d += a*b  (row.col, f32 accum)
__device__ __forceinline__ void mma_tf32(float* d, const uint32_t* a, const uint32_t* b) {
    asm volatile(
        "mma.sync.aligned.m16n8k8.row.col.f32.tf32.tf32.f32 "
        "{%0,%1,%2,%3}, {%4,%5,%6,%7}, {%8,%9}, {%0,%1,%2,%3};"
        : "+f"(d[0]), "+f"(d[1]), "+f"(d[2]), "+f"(d[3])
        : "r"(a[0]), "r"(a[1]), "r"(a[2]), "r"(a[3]), "r"(b[0]), "r"(b[1]));
}

// ---------------------------------------------------------------------------
// Scratch (device globals; no runtime allocation)
// ---------------------------------------------------------------------------
__device__ int   g_count[E_NUM];
__device__ int   g_tok[E_NUM][T_TOK];
__device__ float g_wt [E_NUM][T_TOK];
__device__ float g_x  [T_TOK][H_DIM];             // tf32-rounded x
__device__ float g_act[E_NUM][T_TOK][F_DIM];      // tf32-rounded activations

// ---------------------------------------------------------------------------
__global__ void init_kernel() {
    if (threadIdx.x < E_NUM) g_count[threadIdx.x] = 0;
}

// x -> tf32-rounded copy (vectorized)
__global__ __launch_bounds__(256) void round_x_kernel(const float* __restrict__ x) {
    int i = blockIdx.x * 256 + threadIdx.x;
    float4 v = ((const float4*)x)[i];
    v.x = f2tf32f(v.x); v.y = f2tf32f(v.y);
    v.z = f2tf32f(v.z); v.w = f2tf32f(v.w);
    ((float4*)&g_x[0][0])[i] = v;
}

// zero output (replaces cudaMemsetAsync; also makes launch count stable for ncu)
__global__ __launch_bounds__(256) void zero_out_kernel(float* __restrict__ out) {
    int i = blockIdx.x * 256 + threadIdx.x;
    ((float4*)out)[i] = make_float4(0.f, 0.f, 0.f, 0.f);
}

// Router: one warp per token, top-2 normalized softmax, scatter to expert lists
__global__ __launch_bounds__(256) void router_kernel(
    const float* __restrict__ x, const float* __restrict__ Wr)
{
    int warp = (blockIdx.x * blockDim.x + threadIdx.x) >> 5;
    int lane = threadIdx.x & 31;
    if (warp >= T_TOK) return;

    const float* xr = x + (size_t)warp * H_DIM;
    float acc[E_NUM];
#pragma unroll
    for (int e = 0; e < E_NUM; e++) acc[e] = 0.f;

    for (int h = lane; h < H_DIM; h += 32) {
        float xv = xr[h];
        const float* wr = Wr + (size_t)h * E_NUM;
#pragma unroll
        for (int e = 0; e < E_NUM; e++) acc[e] += xv * wr[e];
    }
#pragma unroll
    for (int e = 0; e < E_NUM; e++) {
#pragma unroll
        for (int off = 16; off; off >>= 1)
            acc[e] += __shfl_xor_sync(0xffffffff, acc[e], off);
    }

    if (lane == 0) {
        int e1 = 0;
#pragma unroll
        for (int e = 1; e < E_NUM; e++) if (acc[e] > acc[e1]) e1 = e;
        int e2 = -1;
#pragma unroll
        for (int e = 0; e < E_NUM; e++) {
            if (e == e1) continue;
            if (e2 < 0 || acc[e] > acc[e2]) e2 = e;
        }
        float l1 = acc[e1], l2 = acc[e2];
        float p2 = 1.f / (1.f + expf(l1 - l2));
        float p1 = 1.f - p2;

        int pos1 = atomicAdd(&g_count[e1], 1);
        g_tok[e1][pos1] = warp; g_wt[e1][pos1] = p1;
        int pos2 = atomicAdd(&g_count[e2], 1);
        g_tok[e2][pos2] = warp; g_wt[e2][pos2] = p2;
    }
}

// ---------------------------------------------------------------------------
// Gate+Up mma.sync GEMM, weights read in NATIVE [K][N] layout (no transpose).
// CTA: M=128 token slots x N=64 f-cols, BOTH gate and up.
// K=H=1024 in 32-float chunks, 2-stage cp.async pipeline.
// Warp grid 4(M) x 2(N): each warp 32 rows x 32 cols per matrix.
// Smem stage: A[128][36] + Bg[32][72] + Bu[32][72] floats.
//   A banks:  (36*g + t) % 32 = (4g+t) % 32  -> perfect permutation
//   B banks:  (72*t + g) % 32 = (8t+g) % 32  -> perfect permutation
// ---------------------------------------------------------------------------
#define GU_A_F   (128 * 36)
#define GU_B_F   (32 * 72)
#define GU_STAGE_F (GU_A_F + 2 * GU_B_F)           // 9216 floats
#define GEMM_SMEM_BYTES (GU_STAGE_F * 4 * 2)       // 73728 bytes

__global__ __launch_bounds__(256) void gateup_mma_kernel(
    const float* __restrict__ Wg, const float* __restrict__ Wu)
{
    int e = blockIdx.z;
    int n_e = g_count[e];
    int row0 = blockIdx.y * 128;
    if (row0 >= n_e) return;
    int n0 = blockIdx.x * 64;

    extern __shared__ float sm[];
    __shared__ int toks[128];
    int tid = threadIdx.x;
    if (tid < 128) {
        int m = row0 + tid;
        toks[tid] = g_tok[e][m < n_e ? m : (n_e - 1)];
    }
    __syncthreads();

    const float* wg_e = Wg + (size_t)e * H_DIM * F_DIM;
    const float* wu_e = Wu + (size_t)e * H_DIM * F_DIM;

    int wid = tid >> 5, lane = tid & 31;
    int wm = wid & 3, wn = wid >> 2;
    int g = lane >> 2, t = lane & 3;

    float accg[2][4][4], accu[2][4][4];
#pragma unroll
    for (int mi = 0; mi < 2; mi++)
#pragma unroll
        for (int nj = 0; nj < 4; nj++)
#pragma unroll
            for (int q = 0; q < 4; q++) { accg[mi][nj][q] = 0.f; accu[mi][nj][q] = 0.f; }

    const int NCH = H_DIM / 32;

#define GU_LOAD(cc, stage) do { \
        int k0 = (cc) * 32; \
        float* base = sm + (stage) * GU_STAGE_F; \
        uint32_t sA = (uint32_t)__cvta_generic_to_shared(base); \
        uint32_t sG = (uint32_t)__cvta_generic_to_shared(base + GU_A_F); \
        uint32_t sU = (uint32_t)__cvta_generic_to_shared(base + GU_A_F + GU_B_F); \
        _Pragma("unroll") \
        for (int i = 0; i < 4; i++) { \
            int idx = tid + i * 256; int r = idx >> 3, c4 = idx & 7; \
            CP_ASYNC16(sA + (uint32_t)(r * 36 + c4 * 4) * 4, &g_x[toks[r]][k0 + c4 * 4]); \
        } \
        _Pragma("unroll") \
        for (int i = 0; i < 2; i++) { \
            int idx = tid + i * 256; int kr = idx >> 4, nc = idx & 15; \
            size_t go = (size_t)(k0 + kr) * F_DIM + n0 + nc * 4; \
            CP_ASYNC16(sG + (uint32_t)(kr * 72 + nc * 4) * 4, wg_e + go); \
            CP_ASYNC16(sU + (uint32_t)(kr * 72 + nc * 4) * 4, wu_e + go); \
        } \
        CP_COMMIT(); \
    } while (0)

    GU_LOAD(0, 0);

#pragma unroll 1
    for (int c = 0; c < NCH; c++) {
        int stage = c & 1;
        if (c + 1 < NCH) { GU_LOAD(c + 1, (c + 1) & 1); CP_WAIT(1); }
        else            { CP_WAIT(0); }
        __syncthreads();

        const float* A  = sm + stage * GU_STAGE_F;
        const float* Bg = A + GU_A_F;
        const float* Bu = Bg + GU_B_F;

#pragma unroll
        for (int ks = 0; ks < 4; ks++) {
            int kb = ks * 8;
            uint32_t a[2][4];
#pragma unroll
            for (int mi = 0; mi < 2; mi++) {
                int r = wm * 32 + mi * 16 + g;
                a[mi][0] = __float_as_uint(A[r * 36 + kb + t]);
                a[mi][1] = __float_as_uint(A[(r + 8) * 36 + kb + t]);
                a[mi][2] = __float_as_uint(A[r * 36 + kb + t + 4]);
                a[mi][3] = __float_as_uint(A[(r + 8) * 36 + kb + t + 4]);
            }
#pragma unroll
            for (int nj = 0; nj < 4; nj++) {
                int n = wn * 32 + nj * 8 + g;
                uint32_t bg[2], bu[2];
                bg[0] = f2tf32u(Bg[(kb + t) * 72 + n]);
                bg[1] = f2tf32u(Bg[(kb + t + 4) * 72 + n]);
                bu[0] = f2tf32u(Bu[(kb + t) * 72 + n]);
                bu[1] = f2tf32u(Bu[(kb + t + 4) * 72 + n]);
#pragma unroll
                for (int mi = 0; mi < 2; mi++) {
                    mma_tf32(accg[mi][nj], a[mi], bg);
                    mma_tf32(accu[mi][nj], a[mi], bu);
                }
            }
        }
        __syncthreads();
    }
#undef GU_LOAD

    // Epilogue: act = silu(gate)*up*w, tf32-rounded -> g_act
#pragma unroll
    for (int mi = 0; mi < 2; mi++) {
#pragma unroll
        for (int half = 0; half < 2; half++) {
            int m = row0 + wm * 32 + mi * 16 + g + half * 8;
            if (m >= n_e) continue;
            float w = g_wt[e][m];
            float* dst = &g_act[e][m][n0 + wn * 32];
#pragma unroll
            for (int nj = 0; nj < 4; nj++) {
                float g0 = accg[mi][nj][half * 2 + 0];
                float g1 = accg[mi][nj][half * 2 + 1];
                float u0 = accu[mi][nj][half * 2 + 0];
                float u1 = accu[mi][nj][half * 2 + 1];
                float s0 = g0 / (1.f + expf(-g0)) * u0 * w;
                float s1 = g1 / (1.f + expf(-g1)) * u1 * w;
                float2 o = make_float2(f2tf32f(s0), f2tf32f(s1));
                *(float2*)(dst + nj * 8 + 2 * t) = o;
            }
        }
    }
}

// ---------------------------------------------------------------------------
// Down mma.sync GEMM + scatter-add, Wd read in NATIVE [K=F][N=H] layout.
// CTA: M=128 slots x N=128 h-cols, K=F=512 in 32-float chunks.
// Warp grid 4(M) x 2(N): each warp 32 rows x 64 cols.
// Smem stage: A[128][36] + B[32][136]
//   B banks: (136*t + g) % 32 = (8t+g) % 32 -> perfect permutation
// ---------------------------------------------------------------------------
#define DN_A_F   (128 * 36)
#define DN_B_F   (32 * 136)
#define DN_STAGE_F (DN_A_F + DN_B_F)               // 8960 floats

__global__ __launch_bounds__(256) void down_mma_kernel(
    const float* __restrict__ Wd, float* __restrict__ out)
{
    int e = blockIdx.z;
    int n_e = g_count[e];
    int row0 = blockIdx.y * 128;
    if (row0 >= n_e) return;
    int n0 = blockIdx.x * 128;

    extern __shared__ float sm[];
    int tid = threadIdx.x;

    const float* a_e = &g_act[e][row0][0];
    const float* b_e = Wd + (size_t)e * F_DIM * H_DIM;

    int wid = tid >> 5, lane = tid & 31;
    int wm = wid & 3, wn = wid >> 2;
    int g = lane >> 2, t = lane & 3;

    float acc[2][8][4];
#pragma unroll
    for (int mi = 0; mi < 2; mi++)
#pragma unroll
        for (int nj = 0; nj < 8; nj++)
#pragma unroll
            for (int q = 0; q < 4; q++) acc[mi][nj][q] = 0.f;

    const int NCH = F_DIM / 32;

#define DN_LOAD(cc, stage) do { \
        int k0 = (cc) * 32; \
        float* base = sm + (stage) * DN_STAGE_F; \
        uint32_t sA = (uint32_t)__cvta_generic_to_shared(base); \
        uint32_t sB = (uint32_t)__cvta_generic_to_shared(base + DN_A_F); \
        _Pragma("unroll") \
        for (int i = 0; i < 4; i++) { \
            int idx = tid + i * 256; int r = idx >> 3, c4 = idx & 7; \
            CP_ASYNC16(sA + (uint32_t)(r * 36 + c4 * 4) * 4, a_e + (size_t)r * F_DIM + k0 + c4 * 4); \
        } \
        _Pragma("unroll") \
        for (int i = 0; i < 4; i++) { \
            int idx = tid + i * 256; int kr = idx >> 5, nc = idx & 31; \
            CP_ASYNC16(sB + (uint32_t)(kr * 136 + nc * 4) * 4, \
                       b_e + (size_t)(k0 + kr) * H_DIM + n0 + nc * 4); \
        } \
        CP_COMMIT(); \
    } while (0)

    DN_LOAD(0, 0);

#pragma unroll 1
    for (int c = 0; c < NCH; c++) {
        int stage = c & 1;
        if (c + 1 < NCH) { DN_LOAD(c + 1, (c + 1) & 1); CP_WAIT(1); }
        else            { CP_WAIT(0); }
        __syncthreads();

        const float* A = sm + stage * DN_STAGE_F;
        const float* B = A + DN_A_F;

#pragma unroll
        for (int ks = 0; ks < 4; ks++) {
            int kb = ks * 8;
            uint32_t a[2][4];
#pragma unroll
            for (int mi = 0; mi < 2; mi++) {
                int r = wm * 32 + mi * 16 + g;
                a[mi][0] = __float_as_uint(A[r * 36 + kb + t]);
                a[mi][1] = __float_as_uint(A[(r + 8) * 36 + kb + t]);
                a[mi][2] = __float_as_uint(A[r * 36 + kb + t + 4]);
                a[mi][3] = __float_as_uint(A[(r + 8) * 36 + kb + t + 4]);
            }
#pragma unroll
            for (int nj = 0; nj < 8; nj++) {
                int n = wn * 64 + nj * 8 + g;
                uint32_t b[2];
                b[0] = f2tf32u(B[(kb + t) * 136 + n]);
                b[1] = f2tf32u(B[(kb + t + 4) * 136 + n]);
#pragma unroll
                for (int mi = 0; mi < 2; mi++)
                    mma_tf32(acc[mi][nj], a[mi], b);
            }
        }
        __syncthreads();
    }
#undef DN_LOAD

    // Epilogue: scatter-add into out rows
#pragma unroll
    for (int mi = 0; mi < 2; mi++) {
#pragma unroll
        for (int half = 0; half < 2; half++) {
            int m = row0 + wm * 32 + mi * 16 + g + half * 8;
            if (m >= n_e) continue;
            int tk = g_tok[e][m];
            float* dst = out + (size_t)tk * H_DIM + n0 + wn * 64;
#pragma unroll
            for (int nj = 0; nj < 8; nj++) {
                atomicAdd(dst + nj * 8 + 2 * t,     acc[mi][nj][half * 2 + 0]);
                atomicAdd(dst + nj * 8 + 2 * t + 1, acc[mi][nj][half * 2 + 1]);
            }
        }
    }
}

// ---------------------------------------------------------------------------
extern "C" void kernel_launch(void* const* d_in, const int* in_sizes, int n_in,
                              void* d_out, int out_size)
{
    const float* x  = (const float*)d_in[0];
    const float* Wr = (const float*)d_in[1];
    const float* Wg = (const float*)d_in[2];
    const float* Wu = (const float*)d_in[3];
    const float* Wd = (const float*)d_in[4];
    float* out = (float*)d_out;

    cudaFuncSetAttribute(gateup_mma_kernel, cudaFuncAttributeMaxDynamicSharedMemorySize, GEMM_SMEM_BYTES);
    cudaFuncSetAttribute(down_mma_kernel,   cudaFuncAttributeMaxDynamicSharedMemorySize, GEMM_SMEM_BYTES);

    // Launch order fixed so ncu (-s 5 -c 1) captures down_mma_kernel (6th kernel).
    init_kernel<<<1, 32>>>();
    round_x_kernel<<<T_TOK * H_DIM / 4 / 256, 256>>>(x);
    router_kernel<<<T_TOK / 8, 256>>>(x, Wr);
    zero_out_kernel<<<(int)((size_t)out_size / 4 / 256), 256>>>(out);

    dim3 g2(F_DIM / 64, T_TOK / 128, E_NUM);
    gateup_mma_kernel<<<g2, 256, GEMM_SMEM_BYTES>>>(Wg, Wu);

    dim3 g3(H_DIM / 128, T_TOK / 128, E_NUM);
    down_mma_kernel<<<g3, 256, GEMM_SMEM_BYTES>>>(Wd, out);
}

// round 10
// speedup vs baseline: 3.7130x; 1.3263x over previous
#include <cuda_runtime.h>
#include <cuda_fp16.h>
#include <math.h>
#include <stdint.h>

// Problem constants (B=2, S=2048 -> T=4096; H=1024; F=512; E=8; TOPK=2)
#define T_TOK 4096
#define H_DIM 1024
#define F_DIM 512
#define E_NUM 8

// ---------------------------------------------------------------------------
// Helpers
// ---------------------------------------------------------------------------
#define CP_ASYNC16(dst_u32, src_ptr) \
    asm volatile("cp.async.cg.shared.global [%0], [%1], 16;" \
        :: "r"(dst_u32), "l"(src_ptr))
#define CP_COMMIT() asm volatile("cp.async.commit_group;")
#define CP_WAIT(n)  asm volatile("cp.async.wait_group %0;" :: "n"(n))

#define LDSM_X4(r0, r1, r2, r3, addr) \
    asm volatile("ldmatrix.sync.aligned.m8n8.x4.shared.b16 {%0,%1,%2,%3}, [%4];" \
        : "=r"(r0), "=r"(r1), "=r"(r2), "=r"(r3) : "r"(addr))

#define LDSM_X4_T(r0, r1, r2, r3, addr) \
    asm volatile("ldmatrix.sync.aligned.m8n8.x4.trans.shared.b16 {%0,%1,%2,%3}, [%4];" \
        : "=r"(r0), "=r"(r1), "=r"(r2), "=r"(r3) : "r"(addr))

// m16n8k16 fp16 MMA, f32 accum: d += a*b (row.col)
__device__ __forceinline__ void mma_f16(float* d, const uint32_t* a, const uint32_t* b) {
    asm volatile(
        "mma.sync.aligned.m16n8k16.row.col.f32.f16.f16.f32 "
        "{%0,%1,%2,%3}, {%4,%5,%6,%7}, {%8,%9}, {%0,%1,%2,%3};"
        : "+f"(d[0]), "+f"(d[1]), "+f"(d[2]), "+f"(d[3])
        : "r"(a[0]), "r"(a[1]), "r"(a[2]), "r"(a[3]), "r"(b[0]), "r"(b[1]));
}

// ---------------------------------------------------------------------------
// Scratch (device globals; no runtime allocation)
// ---------------------------------------------------------------------------
__device__ int    g_count[E_NUM];
__device__ int    g_tok[E_NUM][T_TOK];
__device__ float  g_wt [E_NUM][T_TOK];
__device__ __align__(16) __half g_xh  [T_TOK][H_DIM];          // fp16 x
__device__ __align__(16) __half g_acth[E_NUM][T_TOK][F_DIM];   // fp16 activations
__device__ __align__(16) __half g_wgh [E_NUM][H_DIM][F_DIM];   // fp16 Wg (native [K][N])
__device__ __align__(16) __half g_wuh [E_NUM][H_DIM][F_DIM];   // fp16 Wu
__device__ __align__(16) __half g_wdh [E_NUM][F_DIM][H_DIM];   // fp16 Wd

// ---------------------------------------------------------------------------
__global__ void init_kernel() {
    if (threadIdx.x < E_NUM) g_count[threadIdx.x] = 0;
}

// fp32 -> fp16 convert (4 elems/thread)
__global__ __launch_bounds__(256) void convert_h_kernel(
    const float* __restrict__ in, __half* __restrict__ out)
{
    int i = blockIdx.x * 256 + threadIdx.x;
    float4 v = ((const float4*)in)[i];
    __half2 h0 = __floats2half2_rn(v.x, v.y);
    __half2 h1 = __floats2half2_rn(v.z, v.w);
    uint2 p;
    p.x = *(uint32_t*)&h0; p.y = *(uint32_t*)&h1;
    ((uint2*)out)[i] = p;
}

// zero output
__global__ __launch_bounds__(256) void zero_out_kernel(float* __restrict__ out) {
    int i = blockIdx.x * 256 + threadIdx.x;
    ((float4*)out)[i] = make_float4(0.f, 0.f, 0.f, 0.f);
}

// Router: one warp per token, top-2 normalized softmax
__global__ __launch_bounds__(256) void router_kernel(
    const float* __restrict__ x, const float* __restrict__ Wr)
{
    int warp = (blockIdx.x * blockDim.x + threadIdx.x) >> 5;
    int lane = threadIdx.x & 31;
    if (warp >= T_TOK) return;

    const float* xr = x + (size_t)warp * H_DIM;
    float acc[E_NUM];
#pragma unroll
    for (int e = 0; e < E_NUM; e++) acc[e] = 0.f;

    for (int h = lane; h < H_DIM; h += 32) {
        float xv = xr[h];
        const float* wr = Wr + (size_t)h * E_NUM;
#pragma unroll
        for (int e = 0; e < E_NUM; e++) acc[e] += xv * wr[e];
    }
#pragma unroll
    for (int e = 0; e < E_NUM; e++) {
#pragma unroll
        for (int off = 16; off; off >>= 1)
            acc[e] += __shfl_xor_sync(0xffffffff, acc[e], off);
    }

    if (lane == 0) {
        int e1 = 0;
#pragma unroll
        for (int e = 1; e < E_NUM; e++) if (acc[e] > acc[e1]) e1 = e;
        int e2 = -1;
#pragma unroll
        for (int e = 0; e < E_NUM; e++) {
            if (e == e1) continue;
            if (e2 < 0 || acc[e] > acc[e2]) e2 = e;
        }
        float l1 = acc[e1], l2 = acc[e2];
        float p2 = 1.f / (1.f + expf(l1 - l2));
        float p1 = 1.f - p2;

        int pos1 = atomicAdd(&g_count[e1], 1);
        g_tok[e1][pos1] = warp; g_wt[e1][pos1] = p1;
        int pos2 = atomicAdd(&g_count[e2], 1);
        g_tok[e2][pos2] = warp; g_wt[e2][pos2] = p2;
    }
}

// ---------------------------------------------------------------------------
// Gate+Up fp16 mma GEMM. CTA: M=128 x N=64 f-cols (both matrices).
// K=1024 in 32-half chunks, 2-stage cp.async pipeline.
// Warp grid 4(M) x 2(N); warp tile 32x32 per matrix.
// Smem halves: A[128][40] (stride 80B), Bg[32][72], Bu[32][72] (stride 144B).
//   LDSM phase banks: A 80*r mod 128 distinct; B 144*k mod 128 = 16k distinct.
// ---------------------------------------------------------------------------
#define GU_A_H   (128 * 40)
#define GU_B_H   (32 * 72)
#define GU_STAGE_H (GU_A_H + 2 * GU_B_H)             // 9728 halves
#define GU_SMEM_BYTES (GU_STAGE_H * 2 * 2)           // 38912 bytes
#define DN_A_H   (128 * 40)
#define DN_B_H   (32 * 136)
#define DN_STAGE_H (DN_A_H + DN_B_H)                 // 9472 halves
#define DN_SMEM_BYTES (DN_STAGE_H * 2 * 2)           // 37888 bytes

__global__ __launch_bounds__(256) void gateup_mma_kernel()
{
    int e = blockIdx.z;
    int n_e = g_count[e];
    int row0 = blockIdx.y * 128;
    if (row0 >= n_e) return;
    int n0 = blockIdx.x * 64;

    extern __shared__ __half smh[];
    __shared__ int toks[128];
    int tid = threadIdx.x;
    if (tid < 128) {
        int m = row0 + tid;
        toks[tid] = g_tok[e][m < n_e ? m : (n_e - 1)];
    }
    __syncthreads();

    const __half* wg_e = &g_wgh[e][0][0];
    const __half* wu_e = &g_wuh[e][0][0];

    int wid = tid >> 5, lane = tid & 31;
    int wm = wid & 3, wn = wid >> 2;
    int g = lane >> 2, t = lane & 3;

    float accg[2][4][4], accu[2][4][4];
#pragma unroll
    for (int mi = 0; mi < 2; mi++)
#pragma unroll
        for (int nj = 0; nj < 4; nj++)
#pragma unroll
            for (int q = 0; q < 4; q++) { accg[mi][nj][q] = 0.f; accu[mi][nj][q] = 0.f; }

    // LDSM per-thread offsets (in halves)
    int a_off = (wm * 32 + (lane & 15)) * 40 + (lane >> 4) * 8;          // + mi*640 + kb
    int b_off = (((lane >> 4) & 1) * 8 + (lane & 7)) * 72
              + ((lane >> 3) & 1) * 8;                                    // + kb*72 + nb

    uint32_t sbase = (uint32_t)__cvta_generic_to_shared(smh);
    const int NCH = H_DIM / 32;

#define GU_LOAD(cc, stage) do { \
        int k0 = (cc) * 32; \
        uint32_t sA = sbase + (uint32_t)((stage) * GU_STAGE_H) * 2; \
        uint32_t sG = sA + GU_A_H * 2; \
        uint32_t sU = sG + GU_B_H * 2; \
        _Pragma("unroll") \
        for (int i = 0; i < 2; i++) { \
            int idx = tid + i * 256; int r = idx >> 2, c8 = idx & 3; \
            CP_ASYNC16(sA + (uint32_t)(r * 40 + c8 * 8) * 2, &g_xh[toks[r]][k0 + c8 * 8]); \
        } \
        { \
            int kr = tid >> 3, nc = tid & 7; \
            size_t go = (size_t)(k0 + kr) * F_DIM + n0 + nc * 8; \
            uint32_t so = (uint32_t)(kr * 72 + nc * 8) * 2; \
            CP_ASYNC16(sG + so, wg_e + go); \
            CP_ASYNC16(sU + so, wu_e + go); \
        } \
        CP_COMMIT(); \
    } while (0)

    GU_LOAD(0, 0);

#pragma unroll 1
    for (int c = 0; c < NCH; c++) {
        int stage = c & 1;
        if (c + 1 < NCH) { GU_LOAD(c + 1, (c + 1) & 1); CP_WAIT(1); }
        else            { CP_WAIT(0); }
        __syncthreads();

        uint32_t sA = sbase + (uint32_t)(stage * GU_STAGE_H) * 2;
        uint32_t sG = sA + GU_A_H * 2;
        uint32_t sU = sG + GU_B_H * 2;

#pragma unroll
        for (int ks = 0; ks < 2; ks++) {
            int kb = ks * 16;
            uint32_t a[2][4];
#pragma unroll
            for (int mi = 0; mi < 2; mi++)
                LDSM_X4(a[mi][0], a[mi][1], a[mi][2], a[mi][3],
                        sA + (uint32_t)(a_off + mi * 16 * 40 + kb) * 2);
#pragma unroll
            for (int np = 0; np < 2; np++) {
                int nb = wn * 32 + np * 16;
                uint32_t bg[4], bu[4];
                uint32_t boff = (uint32_t)(b_off + kb * 72 + nb) * 2;
                LDSM_X4_T(bg[0], bg[1], bg[2], bg[3], sG + boff);
                LDSM_X4_T(bu[0], bu[1], bu[2], bu[3], sU + boff);
#pragma unroll
                for (int sub = 0; sub < 2; sub++) {
                    uint32_t bgf[2] = { bg[sub], bg[2 + sub] };
                    uint32_t buf[2] = { bu[sub], bu[2 + sub] };
                    int nj = np * 2 + sub;
#pragma unroll
                    for (int mi = 0; mi < 2; mi++) {
                        mma_f16(accg[mi][nj], a[mi], bgf);
                        mma_f16(accu[mi][nj], a[mi], buf);
                    }
                }
            }
        }
        __syncthreads();
    }
#undef GU_LOAD

    // Epilogue: act = silu(gate)*up*w -> fp16 g_acth
#pragma unroll
    for (int mi = 0; mi < 2; mi++) {
#pragma unroll
        for (int half = 0; half < 2; half++) {
            int m = row0 + wm * 32 + mi * 16 + g + half * 8;
            if (m >= n_e) continue;
            float w = g_wt[e][m];
            __half* dst = &g_acth[e][m][n0 + wn * 32];
#pragma unroll
            for (int nj = 0; nj < 4; nj++) {
                float g0 = accg[mi][nj][half * 2 + 0];
                float g1 = accg[mi][nj][half * 2 + 1];
                float u0 = accu[mi][nj][half * 2 + 0];
                float u1 = accu[mi][nj][half * 2 + 1];
                float s0 = g0 / (1.f + expf(-g0)) * u0 * w;
                float s1 = g1 / (1.f + expf(-g1)) * u1 * w;
                *(__half2*)(dst + nj * 8 + 2 * t) = __floats2half2_rn(s0, s1);
            }
        }
    }
}

// ---------------------------------------------------------------------------
// Down fp16 mma GEMM + scatter-add. CTA: M=128 x N=128 h-cols, K=F=512.
// Warp grid 4(M) x 2(N); warp tile 32x64. Smem: A[128][40] + B[32][136].
// ---------------------------------------------------------------------------
__global__ __launch_bounds__(256) void down_mma_kernel(float* __restrict__ out)
{
    int e = blockIdx.z;
    int n_e = g_count[e];
    int row0 = blockIdx.y * 128;
    if (row0 >= n_e) return;
    int n0 = blockIdx.x * 128;

    extern __shared__ __half smh[];
    int tid = threadIdx.x;

    const __half* a_e = &g_acth[e][row0][0];
    const __half* b_e = &g_wdh[e][0][0];

    int wid = tid >> 5, lane = tid & 31;
    int wm = wid & 3, wn = wid >> 2;
    int g = lane >> 2, t = lane & 3;

    float acc[2][8][4];
#pragma unroll
    for (int mi = 0; mi < 2; mi++)
#pragma unroll
        for (int nj = 0; nj < 8; nj++)
#pragma unroll
            for (int q = 0; q < 4; q++) acc[mi][nj][q] = 0.f;

    int a_off = (wm * 32 + (lane & 15)) * 40 + (lane >> 4) * 8;
    int b_off = (((lane >> 4) & 1) * 8 + (lane & 7)) * 136
              + ((lane >> 3) & 1) * 8;

    uint32_t sbase = (uint32_t)__cvta_generic_to_shared(smh);
    const int NCH = F_DIM / 32;

#define DN_LOAD(cc, stage) do { \
        int k0 = (cc) * 32; \
        uint32_t sA = sbase + (uint32_t)((stage) * DN_STAGE_H) * 2; \
        uint32_t sB = sA + DN_A_H * 2; \
        _Pragma("unroll") \
        for (int i = 0; i < 2; i++) { \
            int idx = tid + i * 256; int r = idx >> 2, c8 = idx & 3; \
            CP_ASYNC16(sA + (uint32_t)(r * 40 + c8 * 8) * 2, \
                       a_e + (size_t)r * F_DIM + k0 + c8 * 8); \
        } \
        _Pragma("unroll") \
        for (int i = 0; i < 2; i++) { \
            int idx = tid + i * 256; int kr = idx >> 4, nc = idx & 15; \
            CP_ASYNC16(sB + (uint32_t)(kr * 136 + nc * 8) * 2, \
                       b_e + (size_t)(k0 + kr) * H_DIM + n0 + nc * 8); \
        } \
        CP_COMMIT(); \
    } while (0)

    DN_LOAD(0, 0);

#pragma unroll 1
    for (int c = 0; c < NCH; c++) {
        int stage = c & 1;
        if (c + 1 < NCH) { DN_LOAD(c + 1, (c + 1) & 1); CP_WAIT(1); }
        else            { CP_WAIT(0); }
        __syncthreads();

        uint32_t sA = sbase + (uint32_t)(stage * DN_STAGE_H) * 2;
        uint32_t sB = sA + DN_A_H * 2;

#pragma unroll
        for (int ks = 0; ks < 2; ks++) {
            int kb = ks * 16;
            uint32_t a[2][4];
#pragma unroll
            for (int mi = 0; mi < 2; mi++)
                LDSM_X4(a[mi][0], a[mi][1], a[mi][2], a[mi][3],
                        sA + (uint32_t)(a_off + mi * 16 * 40 + kb) * 2);
#pragma unroll
            for (int np = 0; np < 4; np++) {
                int nb = wn * 64 + np * 16;
                uint32_t b[4];
                LDSM_X4_T(b[0], b[1], b[2], b[3],
                          sB + (uint32_t)(b_off + kb * 136 + nb) * 2);
#pragma unroll
                for (int sub = 0; sub < 2; sub++) {
                    uint32_t bf[2] = { b[sub], b[2 + sub] };
                    int nj = np * 2 + sub;
#pragma unroll
                    for (int mi = 0; mi < 2; mi++)
                        mma_f16(acc[mi][nj], a[mi], bf);
                }
            }
        }
        __syncthreads();
    }
#undef DN_LOAD

    // Epilogue: scatter-add into out rows
#pragma unroll
    for (int mi = 0; mi < 2; mi++) {
#pragma unroll
        for (int half = 0; half < 2; half++) {
            int m = row0 + wm * 32 + mi * 16 + g + half * 8;
            if (m >= n_e) continue;
            int tk = g_tok[e][m];
            float* dst = out + (size_t)tk * H_DIM + n0 + wn * 64;
#pragma unroll
            for (int nj = 0; nj < 8; nj++) {
                atomicAdd(dst + nj * 8 + 2 * t,     acc[mi][nj][half * 2 + 0]);
                atomicAdd(dst + nj * 8 + 2 * t + 1, acc[mi][nj][half * 2 + 1]);
            }
        }
    }
}

// ---------------------------------------------------------------------------
extern "C" void kernel_launch(void* const* d_in, const int* in_sizes, int n_in,
                              void* d_out, int out_size)
{
    const float* x  = (const float*)d_in[0];
    const float* Wr = (const float*)d_in[1];
    const float* Wg = (const float*)d_in[2];
    const float* Wu = (const float*)d_in[3];
    const float* Wd = (const float*)d_in[4];
    float* out = (float*)d_out;

    cudaFuncSetAttribute(gateup_mma_kernel, cudaFuncAttributeMaxDynamicSharedMemorySize, GU_SMEM_BYTES);
    cudaFuncSetAttribute(down_mma_kernel,   cudaFuncAttributeMaxDynamicSharedMemorySize, DN_SMEM_BYTES);

    __half* xh  = nullptr; cudaGetSymbolAddress((void**)&xh,  g_xh);
    __half* wgh = nullptr; cudaGetSymbolAddress((void**)&wgh, g_wgh);
    __half* wuh = nullptr; cudaGetSymbolAddress((void**)&wuh, g_wuh);
    __half* wdh = nullptr; cudaGetSymbolAddress((void**)&wdh, g_wdh);

    const int WELEM = E_NUM * H_DIM * F_DIM;      // 4M elems per weight tensor

    init_kernel<<<1, 32>>>();
    convert_h_kernel<<<T_TOK * H_DIM / 4 / 256, 256>>>(x, xh);
    router_kernel<<<T_TOK / 8, 256>>>(x, Wr);
    zero_out_kernel<<<(int)((size_t)out_size / 4 / 256), 256>>>(out);
    convert_h_kernel<<<WELEM / 4 / 256, 256>>>(Wg, wgh);
    convert_h_kernel<<<WELEM / 4 / 256, 256>>>(Wu, wuh);
    convert_h_kernel<<<WELEM / 4 / 256, 256>>>(Wd, wdh);

    dim3 g2(F_DIM / 64, T_TOK / 128, E_NUM);
    gateup_mma_kernel<<<g2, 256, GU_SMEM_BYTES>>>();

    dim3 g3(H_DIM / 128, T_TOK / 128, E_NUM);
    down_mma_kernel<<<g3, 256, DN_SMEM_BYTES>>>(out);
}

// round 12
// speedup vs baseline: 3.7927x; 1.0215x over previous
#include <cuda_runtime.h>
#include <cuda_fp16.h>
#include <math.h>
#include <stdint.h>

// Problem constants (B=2, S=2048 -> T=4096; H=1024; F=512; E=8; TOPK=2)
#define T_TOK 4096
#define H_DIM 1024
#define F_DIM 512
#define E_NUM 8

// ---------------------------------------------------------------------------
// Helpers
// ---------------------------------------------------------------------------
#define CP_ASYNC16(dst_u32, src_ptr) \
    asm volatile("cp.async.cg.shared.global [%0], [%1], 16;" \
        :: "r"(dst_u32), "l"(src_ptr))
#define CP_COMMIT() asm volatile("cp.async.commit_group;")
#define CP_WAIT(n)  asm volatile("cp.async.wait_group %0;" :: "n"(n))

#define LDSM_X4(r0, r1, r2, r3, addr) \
    asm volatile("ldmatrix.sync.aligned.m8n8.x4.shared.b16 {%0,%1,%2,%3}, [%4];" \
        : "=r"(r0), "=r"(r1), "=r"(r2), "=r"(r3) : "r"(addr))

#define LDSM_X4_T(r0, r1, r2, r3, addr) \
    asm volatile("ldmatrix.sync.aligned.m8n8.x4.trans.shared.b16 {%0,%1,%2,%3}, [%4];" \
        : "=r"(r0), "=r"(r1), "=r"(r2), "=r"(r3) : "r"(addr))

// m16n8k16 fp16 MMA, f32 accum: d += a*b (row.col)
__device__ __forceinline__ void mma_f16(float* d, const uint32_t* a, const uint32_t* b) {
    asm volatile(
        "mma.sync.aligned.m16n8k16.row.col.f32.f16.f16.f32 "
        "{%0,%1,%2,%3}, {%4,%5,%6,%7}, {%8,%9}, {%0,%1,%2,%3};"
        : "+f"(d[0]), "+f"(d[1]), "+f"(d[2]), "+f"(d[3])
        : "r"(a[0]), "r"(a[1]), "r"(a[2]), "r"(a[3]), "r"(b[0]), "r"(b[1]));
}

// ---------------------------------------------------------------------------
// Scratch (device globals; no runtime allocation)
// ---------------------------------------------------------------------------
__device__ int    g_count[E_NUM];
__device__ int    g_tok[E_NUM][T_TOK];
__device__ float  g_wt [E_NUM][T_TOK];
__device__ __align__(16) __half g_xh  [T_TOK][H_DIM];          // fp16 x
__device__ __align__(16) __half g_acth[E_NUM][T_TOK][F_DIM];   // fp16 activations
__device__ __align__(16) __half g_wgh [E_NUM][H_DIM][F_DIM];   // fp16 Wg (native [K][N])
__device__ __align__(16) __half g_wuh [E_NUM][H_DIM][F_DIM];   // fp16 Wu
__device__ __align__(16) __half g_wdh [E_NUM][F_DIM][H_DIM];   // fp16 Wd

// ---------------------------------------------------------------------------
// Fused convert: x, Wg, Wu, Wd -> fp16 (+ zero expert counters in block 0).
// Each block converts 1024 elements (256 thr x 4). Region split by blockIdx.
// ---------------------------------------------------------------------------
#define XBLKS (T_TOK * H_DIM / 1024)               // 4096
#define WBLKS (E_NUM * H_DIM * F_DIM / 1024)       // 4096

__global__ __launch_bounds__(256) void convert_all_kernel(
    const float* __restrict__ x,  const float* __restrict__ Wg,
    const float* __restrict__ Wu, const float* __restrict__ Wd)
{
    int b = blockIdx.x;
    if (b == 0 && threadIdx.x < E_NUM) g_count[threadIdx.x] = 0;

    const float* src;
    __half* dst;
    int local;
    if (b < XBLKS) {
        src = x;  dst = &g_xh[0][0];  local = b;
    } else if (b < XBLKS + WBLKS) {
        src = Wg; dst = &g_wgh[0][0][0]; local = b - XBLKS;
    } else if (b < XBLKS + 2 * WBLKS) {
        src = Wu; dst = &g_wuh[0][0][0]; local = b - XBLKS - WBLKS;
    } else {
        src = Wd; dst = &g_wdh[0][0][0]; local = b - XBLKS - 2 * WBLKS;
    }
    int i = local * 256 + threadIdx.x;
    float4 v = ((const float4*)src)[i];
    __half2 h0 = __floats2half2_rn(v.x, v.y);
    __half2 h1 = __floats2half2_rn(v.z, v.w);
    uint2 p;
    p.x = *(uint32_t*)&h0; p.y = *(uint32_t*)&h1;
    ((uint2*)dst)[i] = p;
}

// zero output
__global__ __launch_bounds__(256) void zero_out_kernel(float* __restrict__ out) {
    int i = blockIdx.x * 256 + threadIdx.x;
    ((float4*)out)[i] = make_float4(0.f, 0.f, 0.f, 0.f);
}

// Router: one warp per token, top-2 normalized softmax
__global__ __launch_bounds__(256) void router_kernel(
    const float* __restrict__ x, const float* __restrict__ Wr)
{
    int warp = (blockIdx.x * blockDim.x + threadIdx.x) >> 5;
    int lane = threadIdx.x & 31;
    if (warp >= T_TOK) return;

    const float* xr = x + (size_t)warp * H_DIM;
    float acc[E_NUM];
#pragma unroll
    for (int e = 0; e < E_NUM; e++) acc[e] = 0.f;

    for (int h = lane; h < H_DIM; h += 32) {
        float xv = xr[h];
        const float* wr = Wr + (size_t)h * E_NUM;
#pragma unroll
        for (int e = 0; e < E_NUM; e++) acc[e] += xv * wr[e];
    }
#pragma unroll
    for (int e = 0; e < E_NUM; e++) {
#pragma unroll
        for (int off = 16; off; off >>= 1)
            acc[e] += __shfl_xor_sync(0xffffffff, acc[e], off);
    }

    if (lane == 0) {
        int e1 = 0;
#pragma unroll
        for (int e = 1; e < E_NUM; e++) if (acc[e] > acc[e1]) e1 = e;
        int e2 = -1;
#pragma unroll
        for (int e = 0; e < E_NUM; e++) {
            if (e == e1) continue;
            if (e2 < 0 || acc[e] > acc[e2]) e2 = e;
        }
        float l1 = acc[e1], l2 = acc[e2];
        float p2 = 1.f / (1.f + expf(l1 - l2));
        float p1 = 1.f - p2;

        int pos1 = atomicAdd(&g_count[e1], 1);
        g_tok[e1][pos1] = warp; g_wt[e1][pos1] = p1;
        int pos2 = atomicAdd(&g_count[e2], 1);
        g_tok[e2][pos2] = warp; g_wt[e2][pos2] = p2;
    }
}

// ---------------------------------------------------------------------------
// Gate+Up fp16 mma GEMM. CTA: M=128 x N=64 f-cols (both matrices).
// K=1024 in 32-half chunks, 3-stage cp.async pipeline, ONE sync per chunk.
// Warp grid 4(M) x 2(N); warp tile 32x32 per matrix.
// Smem halves per stage: A[128][40], Bg[32][72], Bu[32][72].
// ---------------------------------------------------------------------------
#define GU_A_H   (128 * 40)
#define GU_B_H   (32 * 72)
#define GU_STAGE_H (GU_A_H + 2 * GU_B_H)             // 9728 halves
#define GU_SMEM_BYTES (GU_STAGE_H * 2 * 3)           // 58368 bytes
#define DN_A_H   (128 * 40)
#define DN_B_H   (32 * 136)
#define DN_STAGE_H (DN_A_H + DN_B_H)                 // 9472 halves
#define DN_SMEM_BYTES (DN_STAGE_H * 2 * 3)           // 56832 bytes

__global__ __launch_bounds__(256) void gateup_mma_kernel()
{
    int e = blockIdx.z;
    int n_e = g_count[e];
    int row0 = blockIdx.y * 128;
    if (row0 >= n_e) return;
    int n0 = blockIdx.x * 64;

    extern __shared__ __half smh[];
    __shared__ int toks[128];
    int tid = threadIdx.x;
    if (tid < 128) {
        int m = row0 + tid;
        toks[tid] = g_tok[e][m < n_e ? m : (n_e - 1)];
    }
    __syncthreads();

    const __half* wg_e = &g_wgh[e][0][0];
    const __half* wu_e = &g_wuh[e][0][0];

    int wid = tid >> 5, lane = tid & 31;
    int wm = wid & 3, wn = wid >> 2;
    int g = lane >> 2, t = lane & 3;

    float accg[2][4][4], accu[2][4][4];
#pragma unroll
    for (int mi = 0; mi < 2; mi++)
#pragma unroll
        for (int nj = 0; nj < 4; nj++)
#pragma unroll
            for (int q = 0; q < 4; q++) { accg[mi][nj][q] = 0.f; accu[mi][nj][q] = 0.f; }

    int a_off = (wm * 32 + (lane & 15)) * 40 + (lane >> 4) * 8;
    int b_off = (((lane >> 4) & 1) * 8 + (lane & 7)) * 72
              + ((lane >> 3) & 1) * 8;

    uint32_t sbase = (uint32_t)__cvta_generic_to_shared(smh);
    const int NCH = H_DIM / 32;

#define GU_LOAD(cc, stage) do { \
        int k0 = (cc) * 32; \
        uint32_t sA = sbase + (uint32_t)((stage) * GU_STAGE_H) * 2; \
        uint32_t sG = sA + GU_A_H * 2; \
        uint32_t sU = sG + GU_B_H * 2; \
        _Pragma("unroll") \
        for (int i = 0; i < 2; i++) { \
            int idx = tid + i * 256; int r = idx >> 2, c8 = idx & 3; \
            CP_ASYNC16(sA + (uint32_t)(r * 40 + c8 * 8) * 2, &g_xh[toks[r]][k0 + c8 * 8]); \
        } \
        { \
            int kr = tid >> 3, nc = tid & 7; \
            size_t go = (size_t)(k0 + kr) * F_DIM + n0 + nc * 8; \
            uint32_t so = (uint32_t)(kr * 72 + nc * 8) * 2; \
            CP_ASYNC16(sG + so, wg_e + go); \
            CP_ASYNC16(sU + so, wu_e + go); \
        } \
        CP_COMMIT(); \
    } while (0)

    GU_LOAD(0, 0);
    GU_LOAD(1, 1);

#pragma unroll 1
    for (int c = 0; c < NCH; c++) {
        int stage = c % 3;
        if (c + 2 < NCH) { CP_WAIT(1); } else { CP_WAIT(0); }
        __syncthreads();
        if (c + 2 < NCH) {
            int ns = (c + 2) % 3;
            GU_LOAD(c + 2, ns);
        }

        uint32_t sA = sbase + (uint32_t)(stage * GU_STAGE_H) * 2;
        uint32_t sG = sA + GU_A_H * 2;
        uint32_t sU = sG + GU_B_H * 2;

#pragma unroll
        for (int ks = 0; ks < 2; ks++) {
            int kb = ks * 16;
            uint32_t a[2][4];
#pragma unroll
            for (int mi = 0; mi < 2; mi++)
                LDSM_X4(a[mi][0], a[mi][1], a[mi][2], a[mi][3],
                        sA + (uint32_t)(a_off + mi * 16 * 40 + kb) * 2);
#pragma unroll
            for (int np = 0; np < 2; np++) {
                int nb = wn * 32 + np * 16;
                uint32_t bg[4], bu[4];
                uint32_t boff = (uint32_t)(b_off + kb * 72 + nb) * 2;
                LDSM_X4_T(bg[0], bg[1], bg[2], bg[3], sG + boff);
                LDSM_X4_T(bu[0], bu[1], bu[2], bu[3], sU + boff);
#pragma unroll
                for (int sub = 0; sub < 2; sub++) {
                    uint32_t bgf[2] = { bg[sub], bg[2 + sub] };
                    uint32_t buf[2] = { bu[sub], bu[2 + sub] };
                    int nj = np * 2 + sub;
#pragma unroll
                    for (int mi = 0; mi < 2; mi++) {
                        mma_f16(accg[mi][nj], a[mi], bgf);
                        mma_f16(accu[mi][nj], a[mi], buf);
                    }
                }
            }
        }
    }
#undef GU_LOAD

    // Epilogue: act = silu(gate)*up*w -> fp16 g_acth
#pragma unroll
    for (int mi = 0; mi < 2; mi++) {
#pragma unroll
        for (int half = 0; half < 2; half++) {
            int m = row0 + wm * 32 + mi * 16 + g + half * 8;
            if (m >= n_e) continue;
            float w = g_wt[e][m];
            __half* dst = &g_acth[e][m][n0 + wn * 32];
#pragma unroll
            for (int nj = 0; nj < 4; nj++) {
                float g0 = accg[mi][nj][half * 2 + 0];
                float g1 = accg[mi][nj][half * 2 + 1];
                float u0 = accu[mi][nj][half * 2 + 0];
                float u1 = accu[mi][nj][half * 2 + 1];
                float s0 = g0 / (1.f + expf(-g0)) * u0 * w;
                float s1 = g1 / (1.f + expf(-g1)) * u1 * w;
                *(__half2*)(dst + nj * 8 + 2 * t) = __floats2half2_rn(s0, s1);
            }
        }
    }
}

// ---------------------------------------------------------------------------
// Down fp16 mma GEMM + scatter-add. CTA: M=128 x N=128 h-cols, K=F=512.
// 3-stage pipeline, one sync per chunk. Warp tile 32x64.
// ---------------------------------------------------------------------------
__global__ __launch_bounds__(256) void down_mma_kernel(float* __restrict__ out)
{
    int e = blockIdx.z;
    int n_e = g_count[e];
    int row0 = blockIdx.y * 128;
    if (row0 >= n_e) return;
    int n0 = blockIdx.x * 128;

    extern __shared__ __half smh[];
    int tid = threadIdx.x;

    const __half* a_e = &g_acth[e][row0][0];
    const __half* b_e = &g_wdh[e][0][0];

    int wid = tid >> 5, lane = tid & 31;
    int wm = wid & 3, wn = wid >> 2;
    int g = lane >> 2, t = lane & 3;

    float acc[2][8][4];
#pragma unroll
    for (int mi = 0; mi < 2; mi++)
#pragma unroll
        for (int nj = 0; nj < 8; nj++)
#pragma unroll
            for (int q = 0; q < 4; q++) acc[mi][nj][q] = 0.f;

    int a_off = (wm * 32 + (lane & 15)) * 40 + (lane >> 4) * 8;
    int b_off = (((lane >> 4) & 1) * 8 + (lane & 7)) * 136
              + ((lane >> 3) & 1) * 8;

    uint32_t sbase = (uint32_t)__cvta_generic_to_shared(smh);
    const int NCH = F_DIM / 32;

#define DN_LOAD(cc, stage) do { \
        int k0 = (cc) * 32; \
        uint32_t sA = sbase + (uint32_t)((stage) * DN_STAGE_H) * 2; \
        uint32_t sB = sA + DN_A_H * 2; \
        _Pragma("unroll") \
        for (int i = 0; i < 2; i++) { \
            int idx = tid + i * 256; int r = idx >> 2, c8 = idx & 3; \
            CP_ASYNC16(sA + (uint32_t)(r * 40 + c8 * 8) * 2, \
                       a_e + (size_t)r * F_DIM + k0 + c8 * 8); \
        } \
        _Pragma("unroll") \
        for (int i = 0; i < 2; i++) { \
            int idx = tid + i * 256; int kr = idx >> 4, nc = idx & 15; \
            CP_ASYNC16(sB + (uint32_t)(kr * 136 + nc * 8) * 2, \
                       b_e + (size_t)(k0 + kr) * H_DIM + n0 + nc * 8); \
        } \
        CP_COMMIT(); \
    } while (0)

    DN_LOAD(0, 0);
    DN_LOAD(1, 1);

#pragma unroll 1
    for (int c = 0; c < NCH; c++) {
        int stage = c % 3;
        if (c + 2 < NCH) { CP_WAIT(1); } else { CP_WAIT(0); }
        __syncthreads();
        if (c + 2 < NCH) {
            int ns = (c + 2) % 3;
            DN_LOAD(c + 2, ns);
        }

        uint32_t sA = sbase + (uint32_t)(stage * DN_STAGE_H) * 2;
        uint32_t sB = sA + DN_A_H * 2;

#pragma unroll
        for (int ks = 0; ks < 2; ks++) {
            int kb = ks * 16;
            uint32_t a[2][4];
#pragma unroll
            for (int mi = 0; mi < 2; mi++)
                LDSM_X4(a[mi][0], a[mi][1], a[mi][2], a[mi][3],
                        sA + (uint32_t)(a_off + mi * 16 * 40 + kb) * 2);
#pragma unroll
            for (int np = 0; np < 4; np++) {
                int nb = wn * 64 + np * 16;
                uint32_t b[4];
                LDSM_X4_T(b[0], b[1], b[2], b[3],
                          sB + (uint32_t)(b_off + kb * 136 + nb) * 2);
#pragma unroll
                for (int sub = 0; sub < 2; sub++) {
                    uint32_t bf[2] = { b[sub], b[2 + sub] };
                    int nj = np * 2 + sub;
#pragma unroll
                    for (int mi = 0; mi < 2; mi++)
                        mma_f16(acc[mi][nj], a[mi], bf);
                }
            }
        }
    }
#undef DN_LOAD

    // Epilogue: scatter-add into out rows
#pragma unroll
    for (int mi = 0; mi < 2; mi++) {
#pragma unroll
        for (int half = 0; half < 2; half++) {
            int m = row0 + wm * 32 + mi * 16 + g + half * 8;
            if (m >= n_e) continue;
            int tk = g_tok[e][m];
            float* dst = out + (size_t)tk * H_DIM + n0 + wn * 64;
#pragma unroll
            for (int nj = 0; nj < 8; nj++) {
                atomicAdd(dst + nj * 8 + 2 * t,     acc[mi][nj][half * 2 + 0]);
                atomicAdd(dst + nj * 8 + 2 * t + 1, acc[mi][nj][half * 2 + 1]);
            }
        }
    }
}

// ---------------------------------------------------------------------------
extern "C" void kernel_launch(void* const* d_in, const int* in_sizes, int n_in,
                              void* d_out, int out_size)
{
    const float* x  = (const float*)d_in[0];
    const float* Wr = (const float*)d_in[1];
    const float* Wg = (const float*)d_in[2];
    const float* Wu = (const float*)d_in[3];
    const float* Wd = (const float*)d_in[4];
    float* out = (float*)d_out;

    cudaFuncSetAttribute(gateup_mma_kernel, cudaFuncAttributeMaxDynamicSharedMemorySize, GU_SMEM_BYTES);
    cudaFuncSetAttribute(down_mma_kernel,   cudaFuncAttributeMaxDynamicSharedMemorySize, DN_SMEM_BYTES);

    // Launch order: gateup at index 3 (0-based) so ncu -s 5 -c 1 captures it.
    convert_all_kernel<<<XBLKS + 3 * WBLKS, 256>>>(x, Wg, Wu, Wd);   // 0 (also zeros counters)
    router_kernel<<<T_TOK / 8, 256>>>(x, Wr);                        // 1
    zero_out_kernel<<<(int)((size_t)out_size / 4 / 256), 256>>>(out);// 2

    dim3 g2(F_DIM / 64, T_TOK / 128, E_NUM);
    gateup_mma_kernel<<<g2, 256, GU_SMEM_BYTES>>>();                 // 3  <- ncu target

    dim3 g3(H_DIM / 128, T_TOK / 128, E_NUM);
    down_mma_kernel<<<g3, 256, DN_SMEM_BYTES>>>(out);                // 4
}

// round 15
// speedup vs baseline: 3.8870x; 1.0248x over previous
#include <cuda_runtime.h>
#include <cuda_fp16.h>
#include <math.h>
#include <stdint.h>

// Problem constants (B=2, S=2048 -> T=4096; H=1024; F=512; E=8; TOPK=2)
#define T_TOK 4096
#define H_DIM 1024
#define F_DIM 512
#define E_NUM 8

// ---------------------------------------------------------------------------
// Helpers
// ---------------------------------------------------------------------------
#define CP_ASYNC16(dst_u32, src_ptr) \
    asm volatile("cp.async.cg.shared.global [%0], [%1], 16;" \
        :: "r"(dst_u32), "l"(src_ptr))
#define CP_COMMIT() asm volatile("cp.async.commit_group;")
#define CP_WAIT(n)  asm volatile("cp.async.wait_group %0;" :: "n"(n))

#define LDSM_X4(r0, r1, r2, r3, addr) \
    asm volatile("ldmatrix.sync.aligned.m8n8.x4.shared.b16 {%0,%1,%2,%3}, [%4];" \
        : "=r"(r0), "=r"(r1), "=r"(r2), "=r"(r3) : "r"(addr))

#define LDSM_X4_T(r0, r1, r2, r3, addr) \
    asm volatile("ldmatrix.sync.aligned.m8n8.x4.trans.shared.b16 {%0,%1,%2,%3}, [%4];" \
        : "=r"(r0), "=r"(r1), "=r"(r2), "=r"(r3) : "r"(addr))

// m16n8k16 fp16 MMA, f32 accum: d += a*b (row.col)
__device__ __forceinline__ void mma_f16(float* d, const uint32_t* a, const uint32_t* b) {
    asm volatile(
        "mma.sync.aligned.m16n8k16.row.col.f32.f16.f16.f32 "
        "{%0,%1,%2,%3}, {%4,%5,%6,%7}, {%8,%9}, {%0,%1,%2,%3};"
        : "+f"(d[0]), "+f"(d[1]), "+f"(d[2]), "+f"(d[3])
        : "r"(a[0]), "r"(a[1]), "r"(a[2]), "r"(a[3]), "r"(b[0]), "r"(b[1]));
}

// ---------------------------------------------------------------------------
// Scratch (device globals; no runtime allocation)
// ---------------------------------------------------------------------------
__device__ int    g_count[E_NUM];
__device__ int    g_tok[E_NUM][T_TOK];
__device__ float  g_wt [E_NUM][T_TOK];
__device__ __align__(16) __half g_xh  [T_TOK][H_DIM];          // fp16 x
__device__ __align__(16) __half g_acth[E_NUM][T_TOK][F_DIM];   // fp16 activations
__device__ __align__(16) __half g_wgh [E_NUM][H_DIM][F_DIM];   // fp16 Wg (native [K][N])
__device__ __align__(16) __half g_wuh [E_NUM][H_DIM][F_DIM];   // fp16 Wu
__device__ __align__(16) __half g_wdh [E_NUM][F_DIM][H_DIM];   // fp16 Wd

// ---------------------------------------------------------------------------
// Fused convert: x, Wg, Wu, Wd -> fp16 (+ zero expert counters in block 0).
// ---------------------------------------------------------------------------
#define XBLKS (T_TOK * H_DIM / 1024)               // 4096
#define WBLKS (E_NUM * H_DIM * F_DIM / 1024)       // 4096

__global__ __launch_bounds__(256) void convert_all_kernel(
    const float* __restrict__ x,  const float* __restrict__ Wg,
    const float* __restrict__ Wu, const float* __restrict__ Wd)
{
    int b = blockIdx.x;
    if (b == 0 && threadIdx.x < E_NUM) g_count[threadIdx.x] = 0;

    const float* src;
    __half* dst;
    int local;
    if (b < XBLKS) {
        src = x;  dst = &g_xh[0][0];  local = b;
    } else if (b < XBLKS + WBLKS) {
        src = Wg; dst = &g_wgh[0][0][0]; local = b - XBLKS;
    } else if (b < XBLKS + 2 * WBLKS) {
        src = Wu; dst = &g_wuh[0][0][0]; local = b - XBLKS - WBLKS;
    } else {
        src = Wd; dst = &g_wdh[0][0][0]; local = b - XBLKS - 2 * WBLKS;
    }
    int i = local * 256 + threadIdx.x;
    float4 v = ((const float4*)src)[i];
    __half2 h0 = __floats2half2_rn(v.x, v.y);
    __half2 h1 = __floats2half2_rn(v.z, v.w);
    uint2 p;
    p.x = *(uint32_t*)&h0; p.y = *(uint32_t*)&h1;
    ((uint2*)dst)[i] = p;
}

// zero output
__global__ __launch_bounds__(256) void zero_out_kernel(float* __restrict__ out) {
    int i = blockIdx.x * 256 + threadIdx.x;
    ((float4*)out)[i] = make_float4(0.f, 0.f, 0.f, 0.f);
}

// Router: one warp per token, top-2 normalized softmax
__global__ __launch_bounds__(256) void router_kernel(
    const float* __restrict__ x, const float* __restrict__ Wr)
{
    int warp = (blockIdx.x * blockDim.x + threadIdx.x) >> 5;
    int lane = threadIdx.x & 31;
    if (warp >= T_TOK) return;

    const float* xr = x + (size_t)warp * H_DIM;
    float acc[E_NUM];
#pragma unroll
    for (int e = 0; e < E_NUM; e++) acc[e] = 0.f;

    for (int h = lane; h < H_DIM; h += 32) {
        float xv = xr[h];
        const float* wr = Wr + (size_t)h * E_NUM;
#pragma unroll
        for (int e = 0; e < E_NUM; e++) acc[e] += xv * wr[e];
    }
#pragma unroll
    for (int e = 0; e < E_NUM; e++) {
#pragma unroll
        for (int off = 16; off; off >>= 1)
            acc[e] += __shfl_xor_sync(0xffffffff, acc[e], off);
    }

    if (lane == 0) {
        int e1 = 0;
#pragma unroll
        for (int e = 1; e < E_NUM; e++) if (acc[e] > acc[e1]) e1 = e;
        int e2 = -1;
#pragma unroll
        for (int e = 0; e < E_NUM; e++) {
            if (e == e1) continue;
            if (e2 < 0 || acc[e] > acc[e2]) e2 = e;
        }
        float l1 = acc[e1], l2 = acc[e2];
        float p2 = 1.f / (1.f + __expf(l1 - l2));
        float p1 = 1.f - p2;

        int pos1 = atomicAdd(&g_count[e1], 1);
        g_tok[e1][pos1] = warp; g_wt[e1][pos1] = p1;
        int pos2 = atomicAdd(&g_count[e2], 1);
        g_tok[e2][pos2] = warp; g_wt[e2][pos2] = p2;
    }
}

// ---------------------------------------------------------------------------
// Gate+Up fp16 mma GEMM. CTA: M=128 x N=64 f-cols (both matrices).
// K=1024 in 32-half chunks, 4-stage cp.async pipeline (compile-time stages),
// one sync per chunk; all 12 LDSM of a chunk issued before its 32 MMAs.
// Warp grid 4(M) x 2(N); warp tile 32x32 per matrix.
// ---------------------------------------------------------------------------
#define GU_A_H   (128 * 40)
#define GU_B_H   (32 * 72)
#define GU_STAGE_H (GU_A_H + 2 * GU_B_H)             // 9728 halves
#define GU_SMEM_BYTES (GU_STAGE_H * 2 * 4)           // 77824 bytes
#define DN_A_H   (128 * 40)
#define DN_B_H   (32 * 136)
#define DN_STAGE_H (DN_A_H + DN_B_H)                 // 9472 halves
#define DN_SMEM_BYTES (DN_STAGE_H * 2 * 4)           // 75776 bytes

__global__ __launch_bounds__(256, 2) void gateup_mma_kernel()
{
    int e = blockIdx.z;
    int n_e = g_count[e];
    int row0 = blockIdx.y * 128;
    if (row0 >= n_e) return;
    int n0 = blockIdx.x * 64;

    extern __shared__ __half smh[];
    __shared__ int toks[128];
    int tid = threadIdx.x;
    if (tid < 128) {
        int m = row0 + tid;
        toks[tid] = g_tok[e][m < n_e ? m : (n_e - 1)];
    }
    __syncthreads();

    const __half* wg_e = &g_wgh[e][0][0];
    const __half* wu_e = &g_wuh[e][0][0];

    int wid = tid >> 5, lane = tid & 31;
    int wm = wid & 3, wn = wid >> 2;
    int g = lane >> 2, t = lane & 3;

    float accg[2][4][4], accu[2][4][4];
#pragma unroll
    for (int mi = 0; mi < 2; mi++)
#pragma unroll
        for (int nj = 0; nj < 4; nj++)
#pragma unroll
            for (int q = 0; q < 4; q++) { accg[mi][nj][q] = 0.f; accu[mi][nj][q] = 0.f; }

    int a_off = (wm * 32 + (lane & 15)) * 40 + (lane >> 4) * 8;
    int b_off = (((lane >> 4) & 1) * 8 + (lane & 7)) * 72
              + ((lane >> 3) & 1) * 8;

    uint32_t sbase = (uint32_t)__cvta_generic_to_shared(smh);
    const int NCH = H_DIM / 32;

#define GU_LOAD(cc, stage) do { \
        int k0 = (cc) * 32; \
        uint32_t sA = sbase + (uint32_t)((stage) * GU_STAGE_H) * 2; \
        uint32_t sG = sA + GU_A_H * 2; \
        uint32_t sU = sG + GU_B_H * 2; \
        _Pragma("unroll") \
        for (int i = 0; i < 2; i++) { \
            int idx = tid + i * 256; int r = idx >> 2, c8 = idx & 3; \
            CP_ASYNC16(sA + (uint32_t)(r * 40 + c8 * 8) * 2, &g_xh[toks[r]][k0 + c8 * 8]); \
        } \
        { \
            int kr = tid >> 3, nc = tid & 7; \
            size_t go = (size_t)(k0 + kr) * F_DIM + n0 + nc * 8; \
            uint32_t so = (uint32_t)(kr * 72 + nc * 8) * 2; \
            CP_ASYNC16(sG + so, wg_e + go); \
            CP_ASYNC16(sU + so, wu_e + go); \
        } \
        CP_COMMIT(); \
    } while (0)

    GU_LOAD(0, 0);
    GU_LOAD(1, 1);
    GU_LOAD(2, 2);

#pragma unroll 1
    for (int c = 0; c < NCH; c += 4) {
#pragma unroll
        for (int j = 0; j < 4; j++) {
            int cc = c + j;
            if (cc < NCH - 2) { CP_WAIT(2); } else { CP_WAIT(0); }
            __syncthreads();
            if (cc + 3 < NCH) { GU_LOAD(cc + 3, ((j + 3) & 3)); }

            uint32_t sA = sbase + (uint32_t)(j * GU_STAGE_H) * 2;
            uint32_t sG = sA + GU_A_H * 2;
            uint32_t sU = sG + GU_B_H * 2;

            uint32_t a[2][2][4], bg[2][2][4], bu[2][2][4];
            // Issue ALL 12 LDSM of the chunk before any MMA
#pragma unroll
            for (int ks = 0; ks < 2; ks++) {
                int kb = ks * 16;
#pragma unroll
                for (int mi = 0; mi < 2; mi++)
                    LDSM_X4(a[ks][mi][0], a[ks][mi][1], a[ks][mi][2], a[ks][mi][3],
                            sA + (uint32_t)(a_off + mi * 16 * 40 + kb) * 2);
#pragma unroll
                for (int np = 0; np < 2; np++) {
                    uint32_t boff = (uint32_t)(b_off + kb * 72 + wn * 32 + np * 16) * 2;
                    LDSM_X4_T(bg[ks][np][0], bg[ks][np][1], bg[ks][np][2], bg[ks][np][3], sG + boff);
                    LDSM_X4_T(bu[ks][np][0], bu[ks][np][1], bu[ks][np][2], bu[ks][np][3], sU + boff);
                }
            }
#pragma unroll
            for (int ks = 0; ks < 2; ks++) {
#pragma unroll
                for (int np = 0; np < 2; np++) {
#pragma unroll
                    for (int sub = 0; sub < 2; sub++) {
                        uint32_t bgf[2] = { bg[ks][np][sub], bg[ks][np][2 + sub] };
                        uint32_t buf[2] = { bu[ks][np][sub], bu[ks][np][2 + sub] };
                        int nj = np * 2 + sub;
#pragma unroll
                        for (int mi = 0; mi < 2; mi++) {
                            mma_f16(accg[mi][nj], a[ks][mi], bgf);
                            mma_f16(accu[mi][nj], a[ks][mi], buf);
                        }
                    }
                }
            }
        }
    }
#undef GU_LOAD

    // Epilogue: act = silu(gate)*up*w -> fp16 g_acth
#pragma unroll
    for (int mi = 0; mi < 2; mi++) {
#pragma unroll
        for (int half = 0; half < 2; half++) {
            int m = row0 + wm * 32 + mi * 16 + g + half * 8;
            if (m >= n_e) continue;
            float w = g_wt[e][m];
            __half* dst = &g_acth[e][m][n0 + wn * 32];
#pragma unroll
            for (int nj = 0; nj < 4; nj++) {
                float g0 = accg[mi][nj][half * 2 + 0];
                float g1 = accg[mi][nj][half * 2 + 1];
                float u0 = accu[mi][nj][half * 2 + 0];
                float u1 = accu[mi][nj][half * 2 + 1];
                float s0 = g0 / (1.f + __expf(-g0)) * u0 * w;
                float s1 = g1 / (1.f + __expf(-g1)) * u1 * w;
                *(__half2*)(dst + nj * 8 + 2 * t) = __floats2half2_rn(s0, s1);
            }
        }
    }
}

// ---------------------------------------------------------------------------
// Down fp16 mma GEMM + scatter-add. CTA: M=128 x N=128 h-cols, K=F=512.
// 4-stage pipeline (compile-time stages), batched LDSM, warp tile 32x64.
// ---------------------------------------------------------------------------
__global__ __launch_bounds__(256, 2) void down_mma_kernel(float* __restrict__ out)
{
    int e = blockIdx.z;
    int n_e = g_count[e];
    int row0 = blockIdx.y * 128;
    if (row0 >= n_e) return;
    int n0 = blockIdx.x * 128;

    extern __shared__ __half smh[];
    int tid = threadIdx.x;

    const __half* a_e = &g_acth[e][row0][0];
    const __half* b_e = &g_wdh[e][0][0];

    int wid = tid >> 5, lane = tid & 31;
    int wm = wid & 3, wn = wid >> 2;
    int g = lane >> 2, t = lane & 3;

    float acc[2][8][4];
#pragma unroll
    for (int mi = 0; mi < 2; mi++)
#pragma unroll
        for (int nj = 0; nj < 8; nj++)
#pragma unroll
            for (int q = 0; q < 4; q++) acc[mi][nj][q] = 0.f;

    int a_off = (wm * 32 + (lane & 15)) * 40 + (lane >> 4) * 8;
    int b_off = (((lane >> 4) & 1) * 8 + (lane & 7)) * 136
              + ((lane >> 3) & 1) * 8;

    uint32_t sbase = (uint32_t)__cvta_generic_to_shared(smh);
    const int NCH = F_DIM / 32;

#define DN_LOAD(cc, stage) do { \
        int k0 = (cc) * 32; \
        uint32_t sA = sbase + (uint32_t)((stage) * DN_STAGE_H) * 2; \
        uint32_t sB = sA + DN_A_H * 2; \
        _Pragma("unroll") \
        for (int i = 0; i < 2; i++) { \
            int idx = tid + i * 256; int r = idx >> 2, c8 = idx & 3; \
            CP_ASYNC16(sA + (uint32_t)(r * 40 + c8 * 8) * 2, \
                       a_e + (size_t)r * F_DIM + k0 + c8 * 8); \
        } \
        _Pragma("unroll") \
        for (int i = 0; i < 2; i++) { \
            int idx = tid + i * 256; int kr = idx >> 4, nc = idx & 15; \
            CP_ASYNC16(sB + (uint32_t)(kr * 136 + nc * 8) * 2, \
                       b_e + (size_t)(k0 + kr) * H_DIM + n0 + nc * 8); \
        } \
        CP_COMMIT(); \
    } while (0)

    DN_LOAD(0, 0);
    DN_LOAD(1, 1);
    DN_LOAD(2, 2);

#pragma unroll 1
    for (int c = 0; c < NCH; c += 4) {
#pragma unroll
        for (int j = 0; j < 4; j++) {
            int cc = c + j;
            if (cc < NCH - 2) { CP_WAIT(2); } else { CP_WAIT(0); }
            __syncthreads();
            if (cc + 3 < NCH) { DN_LOAD(cc + 3, ((j + 3) & 3)); }

            uint32_t sA = sbase + (uint32_t)(j * DN_STAGE_H) * 2;
            uint32_t sB = sA + DN_A_H * 2;

            uint32_t a[2][2][4], b[2][4][4];
            // Issue ALL 12 LDSM before MMAs
#pragma unroll
            for (int ks = 0; ks < 2; ks++) {
                int kb = ks * 16;
#pragma unroll
                for (int mi = 0; mi < 2; mi++)
                    LDSM_X4(a[ks][mi][0], a[ks][mi][1], a[ks][mi][2], a[ks][mi][3],
                            sA + (uint32_t)(a_off + mi * 16 * 40 + kb) * 2);
#pragma unroll
                for (int np = 0; np < 4; np++) {
                    uint32_t boff = (uint32_t)(b_off + kb * 136 + wn * 64 + np * 16) * 2;
                    LDSM_X4_T(b[ks][np][0], b[ks][np][1], b[ks][np][2], b[ks][np][3], sB + boff);
                }
            }
#pragma unroll
            for (int ks = 0; ks < 2; ks++) {
#pragma unroll
                for (int np = 0; np < 4; np++) {
#pragma unroll
                    for (int sub = 0; sub < 2; sub++) {
                        uint32_t bf[2] = { b[ks][np][sub], b[ks][np][2 + sub] };
                        int nj = np * 2 + sub;
#pragma unroll
                        for (int mi = 0; mi < 2; mi++)
                            mma_f16(acc[mi][nj], a[ks][mi], bf);
                    }
                }
            }
        }
    }
#undef DN_LOAD

    // Epilogue: scatter-add into out rows
#pragma unroll
    for (int mi = 0; mi < 2; mi++) {
#pragma unroll
        for (int half = 0; half < 2; half++) {
            int m = row0 + wm * 32 + mi * 16 + g + half * 8;
            if (m >= n_e) continue;
            int tk = g_tok[e][m];
            float* dst = out + (size_t)tk * H_DIM + n0 + wn * 64;
#pragma unroll
            for (int nj = 0; nj < 8; nj++) {
                atomicAdd(dst + nj * 8 + 2 * t,     acc[mi][nj][half * 2 + 0]);
                atomicAdd(dst + nj * 8 + 2 * t + 1, acc[mi][nj][half * 2 + 1]);
            }
        }
    }
}

// ---------------------------------------------------------------------------
extern "C" void kernel_launch(void* const* d_in, const int* in_sizes, int n_in,
                              void* d_out, int out_size)
{
    const float* x  = (const float*)d_in[0];
    const float* Wr = (const float*)d_in[1];
    const float* Wg = (const float*)d_in[2];
    const float* Wu = (const float*)d_in[3];
    const float* Wd = (const float*)d_in[4];
    float* out = (float*)d_out;

    cudaFuncSetAttribute(gateup_mma_kernel, cudaFuncAttributeMaxDynamicSharedMemorySize, GU_SMEM_BYTES);
    cudaFuncSetAttribute(down_mma_kernel,   cudaFuncAttributeMaxDynamicSharedMemorySize, DN_SMEM_BYTES);

    // Launch order: gateup at index 3 (0-based) so ncu -s 5 -c 1 captures it.
    convert_all_kernel<<<XBLKS + 3 * WBLKS, 256>>>(x, Wg, Wu, Wd);   // 0 (also zeros counters)
    router_kernel<<<T_TOK / 8, 256>>>(x, Wr);                        // 1
    zero_out_kernel<<<(int)((size_t)out_size / 4 / 256), 256>>>(out);// 2

    dim3 g2(F_DIM / 64, T_TOK / 128, E_NUM);
    gateup_mma_kernel<<<g2, 256, GU_SMEM_BYTES>>>();                 // 3  <- ncu target

    dim3 g3(H_DIM / 128, T_TOK / 128, E_NUM);
    down_mma_kernel<<<g3, 256, DN_SMEM_BYTES>>>(out);                // 4
}

// round 16
// speedup vs baseline: 4.0137x; 1.0326x over previous
#include <cuda_runtime.h>
#include <cuda_fp16.h>
#include <math.h>
#include <stdint.h>

// Problem constants (B=2, S=2048 -> T=4096; H=1024; F=512; E=8; TOPK=2)
#define T_TOK 4096
#define H_DIM 1024
#define F_DIM 512
#define E_NUM 8

// ---------------------------------------------------------------------------
// Helpers
// ---------------------------------------------------------------------------
#define CP_ASYNC16(dst_u32, src_ptr) \
    asm volatile("cp.async.cg.shared.global [%0], [%1], 16;" \
        :: "r"(dst_u32), "l"(src_ptr))
#define CP_COMMIT() asm volatile("cp.async.commit_group;")
#define CP_WAIT(n)  asm volatile("cp.async.wait_group %0;" :: "n"(n))

#define LDSM_X4(r0, r1, r2, r3, addr) \
    asm volatile("ldmatrix.sync.aligned.m8n8.x4.shared.b16 {%0,%1,%2,%3}, [%4];" \
        : "=r"(r0), "=r"(r1), "=r"(r2), "=r"(r3) : "r"(addr))

#define LDSM_X4_T(r0, r1, r2, r3, addr) \
    asm volatile("ldmatrix.sync.aligned.m8n8.x4.trans.shared.b16 {%0,%1,%2,%3}, [%4];" \
        : "=r"(r0), "=r"(r1), "=r"(r2), "=r"(r3) : "r"(addr))

// m16n8k16 fp16 MMA, f32 accum: d += a*b (row.col)
__device__ __forceinline__ void mma_f16(float* d, const uint32_t* a, const uint32_t* b) {
    asm volatile(
        "mma.sync.aligned.m16n8k16.row.col.f32.f16.f16.f32 "
        "{%0,%1,%2,%3}, {%4,%5,%6,%7}, {%8,%9}, {%0,%1,%2,%3};"
        : "+f"(d[0]), "+f"(d[1]), "+f"(d[2]), "+f"(d[3])
        : "r"(a[0]), "r"(a[1]), "r"(a[2]), "r"(a[3]), "r"(b[0]), "r"(b[1]));
}

// ---------------------------------------------------------------------------
// Scratch (device globals; no runtime allocation)
// ---------------------------------------------------------------------------
__device__ int    g_count[E_NUM];
__device__ int    g_tok[E_NUM][T_TOK];
__device__ float  g_wt [E_NUM][T_TOK];
__device__ __align__(16) __half g_xh  [T_TOK][H_DIM];          // fp16 x
__device__ __align__(16) __half g_acth[E_NUM][T_TOK][F_DIM];   // fp16 activations
__device__ __align__(16) __half g_wgh [E_NUM][H_DIM][F_DIM];   // fp16 Wg (native [K][N])
__device__ __align__(16) __half g_wuh [E_NUM][H_DIM][F_DIM];   // fp16 Wu
__device__ __align__(16) __half g_wdh [E_NUM][F_DIM][H_DIM];   // fp16 Wd

// ---------------------------------------------------------------------------
// Fused convert: x, Wg, Wu, Wd -> fp16 (+ zero expert counters in block 0).
// ---------------------------------------------------------------------------
#define XBLKS (T_TOK * H_DIM / 1024)               // 4096
#define WBLKS (E_NUM * H_DIM * F_DIM / 1024)       // 4096

__global__ __launch_bounds__(256) void convert_all_kernel(
    const float* __restrict__ x,  const float* __restrict__ Wg,
    const float* __restrict__ Wu, const float* __restrict__ Wd)
{
    int b = blockIdx.x;
    if (b == 0 && threadIdx.x < E_NUM) g_count[threadIdx.x] = 0;

    const float* src;
    __half* dst;
    int local;
    if (b < XBLKS) {
        src = x;  dst = &g_xh[0][0];  local = b;
    } else if (b < XBLKS + WBLKS) {
        src = Wg; dst = &g_wgh[0][0][0]; local = b - XBLKS;
    } else if (b < XBLKS + 2 * WBLKS) {
        src = Wu; dst = &g_wuh[0][0][0]; local = b - XBLKS - WBLKS;
    } else {
        src = Wd; dst = &g_wdh[0][0][0]; local = b - XBLKS - 2 * WBLKS;
    }
    int i = local * 256 + threadIdx.x;
    float4 v = ((const float4*)src)[i];
    __half2 h0 = __floats2half2_rn(v.x, v.y);
    __half2 h1 = __floats2half2_rn(v.z, v.w);
    uint2 p;
    p.x = *(uint32_t*)&h0; p.y = *(uint32_t*)&h1;
    ((uint2*)dst)[i] = p;
}

// zero output
__global__ __launch_bounds__(256) void zero_out_kernel(float* __restrict__ out) {
    int i = blockIdx.x * 256 + threadIdx.x;
    ((float4*)out)[i] = make_float4(0.f, 0.f, 0.f, 0.f);
}

// Router: one warp per token, top-2 normalized softmax
__global__ __launch_bounds__(256) void router_kernel(
    const float* __restrict__ x, const float* __restrict__ Wr)
{
    int warp = (blockIdx.x * blockDim.x + threadIdx.x) >> 5;
    int lane = threadIdx.x & 31;
    if (warp >= T_TOK) return;

    const float* xr = x + (size_t)warp * H_DIM;
    float acc[E_NUM];
#pragma unroll
    for (int e = 0; e < E_NUM; e++) acc[e] = 0.f;

    for (int h = lane; h < H_DIM; h += 32) {
        float xv = xr[h];
        const float* wr = Wr + (size_t)h * E_NUM;
#pragma unroll
        for (int e = 0; e < E_NUM; e++) acc[e] += xv * wr[e];
    }
#pragma unroll
    for (int e = 0; e < E_NUM; e++) {
#pragma unroll
        for (int off = 16; off; off >>= 1)
            acc[e] += __shfl_xor_sync(0xffffffff, acc[e], off);
    }

    if (lane == 0) {
        int e1 = 0;
#pragma unroll
        for (int e = 1; e < E_NUM; e++) if (acc[e] > acc[e1]) e1 = e;
        int e2 = -1;
#pragma unroll
        for (int e = 0; e < E_NUM; e++) {
            if (e == e1) continue;
            if (e2 < 0 || acc[e] > acc[e2]) e2 = e;
        }
        float l1 = acc[e1], l2 = acc[e2];
        float p2 = 1.f / (1.f + __expf(l1 - l2));
        float p1 = 1.f - p2;

        int pos1 = atomicAdd(&g_count[e1], 1);
        g_tok[e1][pos1] = warp; g_wt[e1][pos1] = p1;
        int pos2 = atomicAdd(&g_count[e2], 1);
        g_tok[e2][pos2] = warp; g_wt[e2][pos2] = p2;
    }
}

// ---------------------------------------------------------------------------
// Gate+Up fp16 mma GEMM. CTA: M=128 x N=64 f-cols (both matrices).
// K=1024 in **64-half chunks** (16 chunks -> 16 barriers), 3-stage cp.async
// pipeline, intra-chunk fragment double-buffering (load ks+1 while ks MMAs).
// Warp grid 4(M) x 2(N); warp tile 32x32 per matrix.
// Smem per stage: A[128][72], Bg[64][72], Bu[64][72] halves.
// ---------------------------------------------------------------------------
#define GU_A_H   (128 * 72)
#define GU_B_H   (64 * 72)
#define GU_STAGE_H (GU_A_H + 2 * GU_B_H)             // 18432 halves
#define GU_SMEM_BYTES (GU_STAGE_H * 2 * 3)           // 110592 bytes
#define DN_A_H   (128 * 72)
#define DN_B_H   (64 * 136)
#define DN_STAGE_H (DN_A_H + DN_B_H)                 // 17920 halves
#define DN_SMEM_BYTES (DN_STAGE_H * 2 * 3)           // 107520 bytes

__global__ __launch_bounds__(256, 2) void gateup_mma_kernel()
{
    int e = blockIdx.z;
    int n_e = g_count[e];
    int row0 = blockIdx.y * 128;
    if (row0 >= n_e) return;
    int n0 = blockIdx.x * 64;

    extern __shared__ __half smh[];
    __shared__ int toks[128];
    int tid = threadIdx.x;
    if (tid < 128) {
        int m = row0 + tid;
        toks[tid] = g_tok[e][m < n_e ? m : (n_e - 1)];
    }
    __syncthreads();

    const __half* wg_e = &g_wgh[e][0][0];
    const __half* wu_e = &g_wuh[e][0][0];

    int wid = tid >> 5, lane = tid & 31;
    int wm = wid & 3, wn = wid >> 2;
    int g = lane >> 2, t = lane & 3;

    float accg[2][4][4], accu[2][4][4];
#pragma unroll
    for (int mi = 0; mi < 2; mi++)
#pragma unroll
        for (int nj = 0; nj < 4; nj++)
#pragma unroll
            for (int q = 0; q < 4; q++) { accg[mi][nj][q] = 0.f; accu[mi][nj][q] = 0.f; }

    int a_off = (wm * 32 + (lane & 15)) * 72 + (lane >> 4) * 8;
    int b_off = (((lane >> 4) & 1) * 8 + (lane & 7)) * 72
              + ((lane >> 3) & 1) * 8;

    uint32_t sbase = (uint32_t)__cvta_generic_to_shared(smh);
    const int NCH = H_DIM / 64;                      // 16 chunks

#define GU_LOAD(cc, stage) do { \
        int k0 = (cc) * 64; \
        uint32_t sA = sbase + (uint32_t)((stage) * GU_STAGE_H) * 2; \
        uint32_t sG = sA + GU_A_H * 2; \
        uint32_t sU = sG + GU_B_H * 2; \
        _Pragma("unroll") \
        for (int i = 0; i < 4; i++) { \
            int idx = tid + i * 256; int r = idx >> 3, c8 = idx & 7; \
            CP_ASYNC16(sA + (uint32_t)(r * 72 + c8 * 8) * 2, &g_xh[toks[r]][k0 + c8 * 8]); \
        } \
        _Pragma("unroll") \
        for (int i = 0; i < 2; i++) { \
            int idx = tid + i * 256; int kr = idx >> 3, nc = idx & 7; \
            size_t go = (size_t)(k0 + kr) * F_DIM + n0 + nc * 8; \
            uint32_t so = (uint32_t)(kr * 72 + nc * 8) * 2; \
            CP_ASYNC16(sG + so, wg_e + go); \
            CP_ASYNC16(sU + so, wu_e + go); \
        } \
        CP_COMMIT(); \
    } while (0)

    // Fragment load for one ks (16 K-halves) into buffer buf
#define GU_FRAG(ksv, buf, sA, sG, sU) do { \
        int kb = (ksv) * 16; \
        _Pragma("unroll") \
        for (int mi = 0; mi < 2; mi++) \
            LDSM_X4(a[buf][mi][0], a[buf][mi][1], a[buf][mi][2], a[buf][mi][3], \
                    (sA) + (uint32_t)(a_off + mi * 16 * 72 + kb) * 2); \
        _Pragma("unroll") \
        for (int np = 0; np < 2; np++) { \
            uint32_t boff = (uint32_t)(b_off + kb * 72 + wn * 32 + np * 16) * 2; \
            LDSM_X4_T(bg[buf][np][0], bg[buf][np][1], bg[buf][np][2], bg[buf][np][3], (sG) + boff); \
            LDSM_X4_T(bu[buf][np][0], bu[buf][np][1], bu[buf][np][2], bu[buf][np][3], (sU) + boff); \
        } \
    } while (0)

#define GU_MMA(buf) do { \
        _Pragma("unroll") \
        for (int np = 0; np < 2; np++) { \
            _Pragma("unroll") \
            for (int sub = 0; sub < 2; sub++) { \
                uint32_t bgf[2] = { bg[buf][np][sub], bg[buf][np][2 + sub] }; \
                uint32_t buf2[2] = { bu[buf][np][sub], bu[buf][np][2 + sub] }; \
                int nj = np * 2 + sub; \
                _Pragma("unroll") \
                for (int mi = 0; mi < 2; mi++) { \
                    mma_f16(accg[mi][nj], a[buf][mi], bgf); \
                    mma_f16(accu[mi][nj], a[buf][mi], buf2); \
                } \
            } \
        } \
    } while (0)

    GU_LOAD(0, 0);
    GU_LOAD(1, 1);

#pragma unroll 1
    for (int c = 0; c < NCH; c++) {
        int stage = c % 3;
        if (c + 2 < NCH) { CP_WAIT(1); } else { CP_WAIT(0); }
        __syncthreads();
        if (c + 2 < NCH) GU_LOAD(c + 2, (c + 2) % 3);

        uint32_t sA = sbase + (uint32_t)(stage * GU_STAGE_H) * 2;
        uint32_t sG = sA + GU_A_H * 2;
        uint32_t sU = sG + GU_B_H * 2;

        uint32_t a[2][2][4], bg[2][2][4], bu[2][2][4];
        GU_FRAG(0, 0, sA, sG, sU);
#pragma unroll
        for (int ks = 0; ks < 4; ks++) {
            if (ks < 3) GU_FRAG(ks + 1, (ks + 1) & 1, sA, sG, sU);
            GU_MMA(ks & 1);
        }
    }
#undef GU_LOAD
#undef GU_FRAG
#undef GU_MMA

    // Epilogue: act = silu(gate)*up*w -> fp16 g_acth
#pragma unroll
    for (int mi = 0; mi < 2; mi++) {
#pragma unroll
        for (int half = 0; half < 2; half++) {
            int m = row0 + wm * 32 + mi * 16 + g + half * 8;
            if (m >= n_e) continue;
            float w = g_wt[e][m];
            __half* dst = &g_acth[e][m][n0 + wn * 32];
#pragma unroll
            for (int nj = 0; nj < 4; nj++) {
                float g0 = accg[mi][nj][half * 2 + 0];
                float g1 = accg[mi][nj][half * 2 + 1];
                float u0 = accu[mi][nj][half * 2 + 0];
                float u1 = accu[mi][nj][half * 2 + 1];
                float s0 = g0 / (1.f + __expf(-g0)) * u0 * w;
                float s1 = g1 / (1.f + __expf(-g1)) * u1 * w;
                *(__half2*)(dst + nj * 8 + 2 * t) = __floats2half2_rn(s0, s1);
            }
        }
    }
}

// ---------------------------------------------------------------------------
// Down fp16 mma GEMM + scatter-add. CTA: M=128 x N=128 h-cols, K=F=512 in
// 64-half chunks (8 barriers). 3-stage pipeline + frag double-buffering.
// Warp grid 4(M) x 2(N); warp tile 32x64.
// ---------------------------------------------------------------------------
__global__ __launch_bounds__(256, 2) void down_mma_kernel(float* __restrict__ out)
{
    int e = blockIdx.z;
    int n_e = g_count[e];
    int row0 = blockIdx.y * 128;
    if (row0 >= n_e) return;
    int n0 = blockIdx.x * 128;

    extern __shared__ __half smh[];
    int tid = threadIdx.x;

    const __half* a_e = &g_acth[e][row0][0];
    const __half* b_e = &g_wdh[e][0][0];

    int wid = tid >> 5, lane = tid & 31;
    int wm = wid & 3, wn = wid >> 2;
    int g = lane >> 2, t = lane & 3;

    float acc[2][8][4];
#pragma unroll
    for (int mi = 0; mi < 2; mi++)
#pragma unroll
        for (int nj = 0; nj < 8; nj++)
#pragma unroll
            for (int q = 0; q < 4; q++) acc[mi][nj][q] = 0.f;

    int a_off = (wm * 32 + (lane & 15)) * 72 + (lane >> 4) * 8;
    int b_off = (((lane >> 4) & 1) * 8 + (lane & 7)) * 136
              + ((lane >> 3) & 1) * 8;

    uint32_t sbase = (uint32_t)__cvta_generic_to_shared(smh);
    const int NCH = F_DIM / 64;                      // 8 chunks

#define DN_LOAD(cc, stage) do { \
        int k0 = (cc) * 64; \
        uint32_t sA = sbase + (uint32_t)((stage) * DN_STAGE_H) * 2; \
        uint32_t sB = sA + DN_A_H * 2; \
        _Pragma("unroll") \
        for (int i = 0; i < 4; i++) { \
            int idx = tid + i * 256; int r = idx >> 3, c8 = idx & 7; \
            CP_ASYNC16(sA + (uint32_t)(r * 72 + c8 * 8) * 2, \
                       a_e + (size_t)r * F_DIM + k0 + c8 * 8); \
        } \
        _Pragma("unroll") \
        for (int i = 0; i < 4; i++) { \
            int idx = tid + i * 256; int kr = idx >> 4, nc = idx & 15; \
            CP_ASYNC16(sB + (uint32_t)(kr * 136 + nc * 8) * 2, \
                       b_e + (size_t)(k0 + kr) * H_DIM + n0 + nc * 8); \
        } \
        CP_COMMIT(); \
    } while (0)

#define DN_FRAG(ksv, buf, sA, sB) do { \
        int kb = (ksv) * 16; \
        _Pragma("unroll") \
        for (int mi = 0; mi < 2; mi++) \
            LDSM_X4(a[buf][mi][0], a[buf][mi][1], a[buf][mi][2], a[buf][mi][3], \
                    (sA) + (uint32_t)(a_off + mi * 16 * 72 + kb) * 2); \
        _Pragma("unroll") \
        for (int np = 0; np < 4; np++) { \
            uint32_t boff = (uint32_t)(b_off + kb * 136 + wn * 64 + np * 16) * 2; \
            LDSM_X4_T(b[buf][np][0], b[buf][np][1], b[buf][np][2], b[buf][np][3], (sB) + boff); \
        } \
    } while (0)

#define DN_MMA(buf) do { \
        _Pragma("unroll") \
        for (int np = 0; np < 4; np++) { \
            _Pragma("unroll") \
            for (int sub = 0; sub < 2; sub++) { \
                uint32_t bf[2] = { b[buf][np][sub], b[buf][np][2 + sub] }; \
                int nj = np * 2 + sub; \
                _Pragma("unroll") \
                for (int mi = 0; mi < 2; mi++) \
                    mma_f16(acc[mi][nj], a[buf][mi], bf); \
            } \
        } \
    } while (0)

    DN_LOAD(0, 0);
    DN_LOAD(1, 1);

#pragma unroll 1
    for (int c = 0; c < NCH; c++) {
        int stage = c % 3;
        if (c + 2 < NCH) { CP_WAIT(1); } else { CP_WAIT(0); }
        __syncthreads();
        if (c + 2 < NCH) DN_LOAD(c + 2, (c + 2) % 3);

        uint32_t sA = sbase + (uint32_t)(stage * DN_STAGE_H) * 2;
        uint32_t sB = sA + DN_A_H * 2;

        uint32_t a[2][2][4], b[2][4][4];
        DN_FRAG(0, 0, sA, sB);
#pragma unroll
        for (int ks = 0; ks < 4; ks++) {
            if (ks < 3) DN_FRAG(ks + 1, (ks + 1) & 1, sA, sB);
            DN_MMA(ks & 1);
        }
    }
#undef DN_LOAD
#undef DN_FRAG
#undef DN_MMA

    // Epilogue: scatter-add into out rows
#pragma unroll
    for (int mi = 0; mi < 2; mi++) {
#pragma unroll
        for (int half = 0; half < 2; half++) {
            int m = row0 + wm * 32 + mi * 16 + g + half * 8;
            if (m >= n_e) continue;
            int tk = g_tok[e][m];
            float* dst = out + (size_t)tk * H_DIM + n0 + wn * 64;
#pragma unroll
            for (int nj = 0; nj < 8; nj++) {
                atomicAdd(dst + nj * 8 + 2 * t,     acc[mi][nj][half * 2 + 0]);
                atomicAdd(dst + nj * 8 + 2 * t + 1, acc[mi][nj][half * 2 + 1]);
            }
        }
    }
}

// ---------------------------------------------------------------------------
extern "C" void kernel_launch(void* const* d_in, const int* in_sizes, int n_in,
                              void* d_out, int out_size)
{
    const float* x  = (const float*)d_in[0];
    const float* Wr = (const float*)d_in[1];
    const float* Wg = (const float*)d_in[2];
    const float* Wu = (const float*)d_in[3];
    const float* Wd = (const float*)d_in[4];
    float* out = (float*)d_out;

    cudaFuncSetAttribute(gateup_mma_kernel, cudaFuncAttributeMaxDynamicSharedMemorySize, GU_SMEM_BYTES);
    cudaFuncSetAttribute(down_mma_kernel,   cudaFuncAttributeMaxDynamicSharedMemorySize, DN_SMEM_BYTES);

    // Launch order: gateup at index 3 (0-based) so ncu -s 5 -c 1 captures it.
    convert_all_kernel<<<XBLKS + 3 * WBLKS, 256>>>(x, Wg, Wu, Wd);   // 0 (also zeros counters)
    router_kernel<<<T_TOK / 8, 256>>>(x, Wr);                        // 1
    zero_out_kernel<<<(int)((size_t)out_size / 4 / 256), 256>>>(out);// 2

    dim3 g2(F_DIM / 64, T_TOK / 128, E_NUM);
    gateup_mma_kernel<<<g2, 256, GU_SMEM_BYTES>>>();                 // 3  <- ncu target

    dim3 g3(H_DIM / 128, T_TOK / 128, E_NUM);
    down_mma_kernel<<<g3, 256, DN_SMEM_BYTES>>>(out);                // 4
}